// round 11
// baseline (speedup 1.0000x reference)
#include <cuda_runtime.h>
#include <cuda_bf16.h>

// Problem dims (fixed by the reference)
#define BB   256      // batch
#define TT   512      // timesteps
#define EE   512      // input dim
#define HH   1024     // hidden dim
#define LDR  ((long)TT * HH)   // row stride between batches in d_out

#define NCTA 128      // persistent CTAs: 4 M-tiles (64 rows) x 32 N-tiles (32 cols)

// ---------------------------------------------------------------------------
// Scratch (device globals; no allocation allowed)
// g_Ap[buf][(tile*128 + g)*32 + lane] : hidden state in PRE-PERMUTED mma
//   fragment layout (see round 9). 4 rotating buffers (slack-3 dataflow).
// ---------------------------------------------------------------------------
__device__ uint4 g_Ap[4][16 * 128 * 32];
__device__ __nv_bfloat16 g_Wkn[2048][HH];    // Whh: [k][n], hi rows 0..1023, lo 1024..2047
__device__ __nv_bfloat16 g_Wx[1024][HH];     // Wxh: [k][n], hi then lo

// dataflow flags: g_rdy[bm*32+bn] = last step whose fragments are published
//                 g_cns[bm*32+bn] = last mainloop completed (fragments consumed)
__device__ int g_rdy[128];
__device__ int g_cns[128];

__global__ void flag_reset() {
    if (threadIdx.x < 128) { g_rdy[threadIdx.x] = 0; g_cns[threadIdx.x] = 0; }
}

// ---------------------------------------------------------------------------
// PTX helpers
// ---------------------------------------------------------------------------
__device__ __forceinline__ unsigned smem_u32(const void* p) {
    unsigned a;
    asm("{ .reg .u64 t; cvta.to.shared.u64 t, %1; cvt.u32.u64 %0, t; }"
        : "=r"(a) : "l"(p));
    return a;
}

__device__ __forceinline__ int acq_ld(const int* p) {
    int v;
    asm volatile("ld.acquire.gpu.global.b32 %0, [%1];" : "=r"(v) : "l"(p));
    return v;
}
__device__ __forceinline__ void rel_st(int* p, int v) {
    asm volatile("st.release.gpu.global.b32 [%0], %1;" :: "l"(p), "r"(v) : "memory");
}

#define LDSM4(r, a) \
    asm volatile("ldmatrix.sync.aligned.m8n8.x4.shared.b16 {%0,%1,%2,%3}, [%4];" \
        : "=r"((r)[0]), "=r"((r)[1]), "=r"((r)[2]), "=r"((r)[3]) : "r"(a))

#define LDSM4T(r, a) \
    asm volatile("ldmatrix.sync.aligned.m8n8.x4.trans.shared.b16 {%0,%1,%2,%3}, [%4];" \
        : "=r"((r)[0]), "=r"((r)[1]), "=r"((r)[2]), "=r"((r)[3]) : "r"(a))

__device__ __forceinline__ void mma16816(float* d, const unsigned* a,
                                         unsigned b0, unsigned b1) {
    asm volatile(
        "mma.sync.aligned.m16n8k16.row.col.f32.bf16.bf16.f32 "
        "{%0,%1,%2,%3}, {%4,%5,%6,%7}, {%8,%9}, {%0,%1,%2,%3};"
        : "+f"(d[0]), "+f"(d[1]), "+f"(d[2]), "+f"(d[3])
        : "r"(a[0]), "r"(a[1]), "r"(a[2]), "r"(a[3]), "r"(b0), "r"(b1));
}

// pack 8 fp32 -> uint4 hi bf16, uint4 lo bf16
__device__ __forceinline__ void split8(float4 a, float4 b, uint4& hi, uint4& lo) {
    float s[8] = {a.x, a.y, a.z, a.w, b.x, b.y, b.z, b.w};
    unsigned h[4], l[4];
    #pragma unroll
    for (int i = 0; i < 4; i++) {
        __nv_bfloat16 h0 = __float2bfloat16(s[2 * i]);
        __nv_bfloat16 h1 = __float2bfloat16(s[2 * i + 1]);
        __nv_bfloat16 l0 = __float2bfloat16(s[2 * i] - __bfloat162float(h0));
        __nv_bfloat16 l1 = __float2bfloat16(s[2 * i + 1] - __bfloat162float(h1));
        h[i] = (unsigned)__bfloat16_as_ushort(h0)
             | ((unsigned)__bfloat16_as_ushort(h1) << 16);
        l[i] = (unsigned)__bfloat16_as_ushort(l0)
             | ((unsigned)__bfloat16_as_ushort(l1) << 16);
    }
    hi = make_uint4(h[0], h[1], h[2], h[3]);
    lo = make_uint4(l[0], l[1], l[2], l[3]);
}

// ---------------------------------------------------------------------------
// Prep: weight conversions + h0
// ---------------------------------------------------------------------------
__global__ void __launch_bounds__(256)
wt_convert(const float* __restrict__ Whh)
{
    int idx = blockIdx.x * 256 + threadIdx.x;
    int k = idx >> 10, n = idx & 1023;
    float w = Whh[(long)k * HH + n];
    __nv_bfloat16 hi = __float2bfloat16(w);
    __nv_bfloat16 lo = __float2bfloat16(w - __bfloat162float(hi));
    g_Wkn[k][n] = hi;
    g_Wkn[1024 + k][n] = lo;
}

__global__ void __launch_bounds__(256)
wx_convert(const float* __restrict__ Wxh)
{
    int idx = blockIdx.x * 256 + threadIdx.x;
    int k = idx >> 10, n = idx & 1023;
    float w = Wxh[(long)k * HH + n];
    __nv_bfloat16 hi = __float2bfloat16(w);
    __nv_bfloat16 lo = __float2bfloat16(w - __bfloat162float(hi));
    g_Wx[k][n] = hi;
    g_Wx[512 + k][n] = lo;
}

// h_0 = relu(xh_0) in place + permuted bf16 hi/lo fragments into g_Ap[0]
__global__ void __launch_bounds__(256)
init_h0(float* __restrict__ out)
{
    int idx = blockIdx.x * 256 + threadIdx.x;   // 0 .. 128K-1
    int b  = idx >> 9;                          // 0..255
    int c2 = (idx & 511) * 2;                   // even col 0..1022
    float* p = out + (long)b * LDR + c2;
    float v0 = fmaxf(p[0], 0.f);
    float v1 = fmaxf(p[1], 0.f);
    p[0] = v0; p[1] = v1;

    __nv_bfloat16 h0 = __float2bfloat16(v0);
    __nv_bfloat16 h1 = __float2bfloat16(v1);
    unsigned hw = (unsigned)__bfloat16_as_ushort(h0)
                | ((unsigned)__bfloat16_as_ushort(h1) << 16);
    __nv_bfloat16 l0 = __float2bfloat16(v0 - __bfloat162float(h0));
    __nv_bfloat16 l1 = __float2bfloat16(v1 - __bfloat162float(h1));
    unsigned lw = (unsigned)__bfloat16_as_ushort(l0)
                | ((unsigned)__bfloat16_as_ushort(l1) << 16);

    int tile = b >> 4;
    int rloc = b & 15;
    int g    = c2 >> 4;
    int cb   = c2 & 15;
    int L    = ((rloc & 7) << 2) + ((cb & 7) >> 1);
    int slot = ((rloc & 8) ? 1 : 0) | ((cb & 8) ? 2 : 0);

    unsigned* dh = (unsigned*)&g_Ap[0][(tile * 128 + g) * 32 + L];
    unsigned* dl = (unsigned*)&g_Ap[0][(tile * 128 + 64 + g) * 32 + L];
    dh[slot] = hw;
    dl[slot] = lw;
}

// ---------------------------------------------------------------------------
// Phase 1 (tensor): xh = x @ Wxh + bxh  (unchanged from round 6-10)
// ---------------------------------------------------------------------------
extern __shared__ char smx[];

#define AFX(kg, m) ((unsigned)((kg) * 2048 + ((m) >> 3) * 128 + ((((m) & 7) ^ (kg)) * 16)))

__global__ void __launch_bounds__(256)
gemm_xh_mma(const float* __restrict__ x,     // [131072, 512]
            const float* __restrict__ bias,  // [1024]
            float* __restrict__ C)           // [131072, 1024]
{
    const int tid  = threadIdx.x;
    const int wid  = tid >> 5;
    const int lane = tid & 31;
    const int wr   = wid & 3;
    const int wc   = wid >> 2;
    const int bm   = blockIdx.y;
    const int bn   = blockIdx.x;

    const unsigned sb = smem_u32(smx);
    const int q   = lane >> 3;
    const int l7  = lane & 7;
    const int kgq = q >> 1;

    const int am = tid & 127;
    const int wk = tid & 31;

    float2 breg[8];
    #pragma unroll
    for (int n8 = 0; n8 < 8; n8++)
        breg[n8] = *(const float2*)&bias[bn * 128 + wc * 64 + n8 * 8 + (lane & 3) * 2];

    float acc[2][8][4];
    #pragma unroll
    for (int m = 0; m < 2; m++)
        #pragma unroll
        for (int n = 0; n < 8; n++)
            #pragma unroll
            for (int j = 0; j < 4; j++) acc[m][n][j] = 0.f;

    const float* xb = x + (long)(bm * 128) * EE;

    float4 xa[2][2];
    uint4  wvh[2], wvl[2];
    #pragma unroll
    for (int i = 0; i < 2; i++) {
        int idx = tid + i * 256;
        int kg = idx >> 7;
        const float* p = xb + (long)am * EE + kg * 8;
        xa[i][0] = *(const float4*)p;
        xa[i][1] = *(const float4*)(p + 4);
        int pp = (idx >> 5) & 15;
        wvh[i] = *(const uint4*)&g_Wx[wk][bn * 128 + pp * 8];
        wvl[i] = *(const uint4*)&g_Wx[512 + wk][bn * 128 + pp * 8];
    }
    #pragma unroll
    for (int i = 0; i < 2; i++) {
        int idx = tid + i * 256;
        int kg = idx >> 7;
        uint4 hi, lo;
        split8(xa[i][0], xa[i][1], hi, lo);
        unsigned ao = AFX(kg, am);
        *(uint4*)(smx + ao)         = hi;
        *(uint4*)(smx + 8192 + ao)  = lo;
        int pp = (idx >> 5) & 15;
        unsigned wo = 16384u + (unsigned)pp * 512u + (unsigned)wk * 16u;
        *(uint4*)(smx + wo)         = wvh[i];
        *(uint4*)(smx + 8192 + wo)  = wvl[i];
    }
    __syncthreads();

    unsigned buf = 0;
    for (int kc = 0; kc < 16; kc++) {
        const bool more = (kc + 1 < 16);
        if (more) {
            const int k0 = (kc + 1) * 32;
            #pragma unroll
            for (int i = 0; i < 2; i++) {
                int idx = tid + i * 256;
                int kg = idx >> 7;
                const float* p = xb + (long)am * EE + k0 + kg * 8;
                xa[i][0] = *(const float4*)p;
                xa[i][1] = *(const float4*)(p + 4);
                int pp = (idx >> 5) & 15;
                wvh[i] = *(const uint4*)&g_Wx[k0 + wk][bn * 128 + pp * 8];
                wvl[i] = *(const uint4*)&g_Wx[512 + k0 + wk][bn * 128 + pp * 8];
            }
        }

        const unsigned B0 = sb + buf * 32768u;
        #pragma unroll
        for (int s16 = 0; s16 < 2; s16++) {
            const int kg = s16 * 2 + kgq;
            const unsigned aoff = (unsigned)kg * 2048u + (unsigned)((l7 ^ kg) * 16);
            unsigned ahi[2][4], alo[2][4];
            LDSM4(ahi[0], B0 + aoff + (unsigned)(wr * 4 + 0 + (q & 1)) * 128u);
            LDSM4(ahi[1], B0 + aoff + (unsigned)(wr * 4 + 2 + (q & 1)) * 128u);
            LDSM4(alo[0], B0 + 8192u + aoff + (unsigned)(wr * 4 + 0 + (q & 1)) * 128u);
            LDSM4(alo[1], B0 + 8192u + aoff + (unsigned)(wr * 4 + 2 + (q & 1)) * 128u);

            const unsigned wrow = (unsigned)(s16 * 16 + (q & 1) * 8 + l7) * 16u;
            #pragma unroll
            for (int pp = 0; pp < 4; pp++) {
                unsigned wh[4], wl[4];
                unsigned wbase = B0 + 16384u
                               + (unsigned)(wc * 8 + pp * 2 + kgq) * 512u + wrow;
                LDSM4T(wh, wbase);
                LDSM4T(wl, wbase + 8192u);
                const int n0 = pp * 2, n1 = pp * 2 + 1;
                mma16816(acc[0][n0], ahi[0], wh[0], wh[1]);
                mma16816(acc[0][n1], ahi[0], wh[2], wh[3]);
                mma16816(acc[1][n0], ahi[1], wh[0], wh[1]);
                mma16816(acc[1][n1], ahi[1], wh[2], wh[3]);
                mma16816(acc[0][n0], alo[0], wh[0], wh[1]);
                mma16816(acc[0][n1], alo[0], wh[2], wh[3]);
                mma16816(acc[1][n0], alo[1], wh[0], wh[1]);
                mma16816(acc[1][n1], alo[1], wh[2], wh[3]);
                mma16816(acc[0][n0], ahi[0], wl[0], wl[1]);
                mma16816(acc[0][n1], ahi[0], wl[2], wl[3]);
                mma16816(acc[1][n0], ahi[1], wl[0], wl[1]);
                mma16816(acc[1][n1], ahi[1], wl[2], wl[3]);
            }
        }

        if (more) {
            const unsigned nb = (buf ^ 1u) * 32768u;
            #pragma unroll
            for (int i = 0; i < 2; i++) {
                int idx = tid + i * 256;
                int kg = idx >> 7;
                uint4 hi, lo;
                split8(xa[i][0], xa[i][1], hi, lo);
                unsigned ao = nb + AFX(kg, am);
                *(uint4*)(smx + ao)        = hi;
                *(uint4*)(smx + 8192 + ao) = lo;
                int pp = (idx >> 5) & 15;
                unsigned wo = nb + 16384u + (unsigned)pp * 512u + (unsigned)wk * 16u;
                *(uint4*)(smx + wo)        = wvh[i];
                *(uint4*)(smx + 8192 + wo) = wvl[i];
            }
            __syncthreads();
            buf ^= 1u;
        }
    }

    #pragma unroll
    for (int mm = 0; mm < 2; mm++) {
        #pragma unroll
        for (int half = 0; half < 2; half++) {
            long row = (long)bm * 128 + wr * 32 + mm * 16 + (lane >> 2) + half * 8;
            float* pr = C + row * HH + bn * 128 + wc * 64 + (lane & 3) * 2;
            #pragma unroll
            for (int n8 = 0; n8 < 8; n8++) {
                float2 o;
                o.x = acc[mm][n8][half * 2 + 0] + breg[n8].x;
                o.y = acc[mm][n8][half * 2 + 1] + breg[n8].y;
                *(float2*)(pr + n8 * 8) = o;
            }
        }
    }
}

// ---------------------------------------------------------------------------
// Phase 2: persistent mma.sync scan — fragment-resident state + slack-3
// producer/consumer dataflow (no grid barrier).
// ---------------------------------------------------------------------------
__global__ void __launch_bounds__(256, 1)
rnn_scan_mma(float* __restrict__ out)
{
    const int tid  = threadIdx.x;
    const int kq   = tid >> 5;          // warp = k16-granule owner 0..7
    const int lane = tid & 31;
    const int bm   = blockIdx.x >> 5;   // 0..3
    const int bn   = blockIdx.x & 31;   // 0..31

    const unsigned sb = smem_u32(smx);

    // ---- stage W slice into SMEM panels (once): hi @0, lo @65536 ----
    for (int i = 0; i < 32; i++) {
        int kk = i * 64 + (tid >> 2);      // 0..2047 packed k
        int p  = tid & 3;                  // n8 panel
        uint4 v = *(const uint4*)&g_Wkn[kk][bn * 32 + p * 8];
        unsigned off = (unsigned)(kk >> 10) * 65536u
                     + (unsigned)p * 16384u + (unsigned)(kk & 1023) * 16u;
        *(uint4*)(smx + off) = v;
    }
    __syncthreads();

    // W ldmatrix lane addressing
    const int q   = lane >> 3;
    const int l7  = lane & 7;
    const int kgq = q >> 1;
    const unsigned wrowsel = (unsigned)((q & 1) * 8 + l7) * 16u;
    const unsigned whiBase = sb + (unsigned)kgq * 16384u + wrowsel;
    const unsigned wloBase = whiBase + 65536u;

    // partial-store mapping
    const int eg = lane >> 2;           // 0..7
    const int ei = lane & 3;            // 0..3
    // reduction / epilogue mapping
    const int r64 = tid >> 2;           // 0..63
    const int n0  = (tid & 3) * 8;      // 0,8,16,24

    const int bm4 = bm * 4;
    int* const rdyBase = &g_rdy[bm * 32];
    int* const cnsBase = &g_cns[bm * 32];

    // epilogue constants
    const int gb    = bm * 64 + r64;
    const int tileE = gb >> 4;
    const int rloc  = gb & 15;
    const int Cb    = bn * 32 + n0;
    const int gE    = Cb >> 4;
    const int slot  = ((rloc & 8) ? 1 : 0) | ((Cb & 8) ? 2 : 0);

    for (int t = 1; t < TT; t++) {
        const uint4* Ab = &g_Ap[(t - 1) & 3][0];

        // prefetch the xh slice for this step (h-independent; hides DRAM)
        float* po = out + (long)gb * LDR + (long)t * HH + Cb;
        float4 x0p = *(const float4*)po;
        float4 x1p = *(const float4*)(po + 4);

        float d[4][4][4];                // [mi][n8][frag]
        #pragma unroll
        for (int mi = 0; mi < 4; mi++)
            #pragma unroll
            for (int nt = 0; nt < 4; nt++)
                #pragma unroll
                for (int j = 0; j < 4; j++) d[mi][nt][j] = 0.f;

        // ---- fast-path readiness: are all producers done with t-1? ----
        bool all_ready;
        {
            int rl = acq_ld(rdyBase + lane);
            all_ready = (__ballot_sync(0xffffffffu, rl >= t - 1) == 0xffffffffu);
        }
        const int pq = kq >> 1;            // producer stride base

        uint4 cur[8], nxt[8];

        // wait + prefetch granule-set 0 (producer p = pq)
        if (!all_ready) {
            while (acq_ld(rdyBase + pq) < t - 1) __nanosleep(64);
        }
        #pragma unroll
        for (int mi = 0; mi < 4; mi++) {
            cur[mi * 2 + 0] = Ab[((bm4 + mi) * 128 + kq) * 32 + lane];
            cur[mi * 2 + 1] = Ab[((bm4 + mi) * 128 + 64 + kq) * 32 + lane];
        }

        #pragma unroll
        for (int i = 0; i < 8; i++) {
            if (i < 7) {
                if (!all_ready) {
                    const int p1 = (i + 1) * 4 + pq;
                    while (acq_ld(rdyBase + p1) < t - 1) __nanosleep(64);
                }
                const int gk1 = (i + 1) * 8 + kq;
                #pragma unroll
                for (int mi = 0; mi < 4; mi++) {
                    nxt[mi * 2 + 0] = Ab[((bm4 + mi) * 128 + gk1) * 32 + lane];
                    nxt[mi * 2 + 1] = Ab[((bm4 + mi) * 128 + 64 + gk1) * 32 + lane];
                }
            }

            const int gk = i * 8 + kq;
            const unsigned wko = (unsigned)gk * 256u;
            unsigned wh1[4], wh2[4], wl1[4], wl2[4];
            LDSM4T(wh1, whiBase + wko);
            LDSM4T(wh2, whiBase + 32768u + wko);
            LDSM4T(wl1, wloBase + wko);
            LDSM4T(wl2, wloBase + 32768u + wko);

            #pragma unroll
            for (int mi = 0; mi < 4; mi++) {
                const unsigned* ahi = (const unsigned*)&cur[mi * 2 + 0];
                const unsigned* alo = (const unsigned*)&cur[mi * 2 + 1];
                mma16816(d[mi][0], ahi, wh1[0], wh1[1]);
                mma16816(d[mi][1], ahi, wh1[2], wh1[3]);
                mma16816(d[mi][2], ahi, wh2[0], wh2[1]);
                mma16816(d[mi][3], ahi, wh2[2], wh2[3]);
                mma16816(d[mi][0], ahi, wl1[0], wl1[1]);
                mma16816(d[mi][1], ahi, wl1[2], wl1[3]);
                mma16816(d[mi][2], ahi, wl2[0], wl2[1]);
                mma16816(d[mi][3], ahi, wl2[2], wl2[3]);
                mma16816(d[mi][0], alo, wh1[0], wh1[1]);
                mma16816(d[mi][1], alo, wh1[2], wh1[3]);
                mma16816(d[mi][2], alo, wh2[0], wh2[1]);
                mma16816(d[mi][3], alo, wh2[2], wh2[3]);
            }

            if (i < 7) {
                #pragma unroll
                for (int j = 0; j < 8; j++) cur[j] = nxt[j];
            }
        }

        // ---- store 64x32 fp32 partial (XOR-16 swizzle on rows) @128KB ----
        {
            const unsigned pb = 131072u + (unsigned)(kq * 8192);
            #pragma unroll
            for (int mi = 0; mi < 4; mi++) {
                #pragma unroll
                for (int half = 0; half < 2; half++) {
                    const int r = mi * 16 + eg + half * 8;   // 0..63
                    const unsigned xr = (unsigned)((r & 7) * 16);
                    #pragma unroll
                    for (int nt = 0; nt < 4; nt++) {
                        float2 pv;
                        pv.x = d[mi][nt][half * 2 + 0];
                        pv.y = d[mi][nt][half * 2 + 1];
                        unsigned cb = (unsigned)(nt * 32 + ei * 8) ^ xr;
                        *(float2*)(smx + pb + (unsigned)r * 128u + cb) = pv;
                    }
                }
            }
        }
        __syncthreads();              // all warps done: mainloop reads + partials

        // publish consumption of buffer (t-1)&3 ASAP (unblocks producers)
        if (tid == 0) rel_st(cnsBase + bn, t);

        // ---- reduce 8 partials + epilogue compute ----
        float4 o0, o1;
        {
            const unsigned xr = (unsigned)((r64 & 7) * 16);
            const unsigned c0 = ((unsigned)(n0 * 4)) ^ xr;
            const unsigned c1 = ((unsigned)(n0 * 4 + 16)) ^ xr;
            float4 s0 = {0.f, 0.f, 0.f, 0.f}, s1 = {0.f, 0.f, 0.f, 0.f};
            #pragma unroll
            for (int p = 0; p < 8; p++) {
                const char* pp = smx + 131072u + (unsigned)(p * 8192)
                               + (unsigned)r64 * 128u;
                float4 a = *(const float4*)(pp + c0);
                float4 b = *(const float4*)(pp + c1);
                s0.x += a.x; s0.y += a.y; s0.z += a.z; s0.w += a.w;
                s1.x += b.x; s1.y += b.y; s1.z += b.z; s1.w += b.w;
            }

            o0.x = fmaxf(x0p.x + s0.x, 0.f); o0.y = fmaxf(x0p.y + s0.y, 0.f);
            o0.z = fmaxf(x0p.z + s0.z, 0.f); o0.w = fmaxf(x0p.w + s0.w, 0.f);
            o1.x = fmaxf(x1p.x + s1.x, 0.f); o1.y = fmaxf(x1p.y + s1.y, 0.f);
            o1.z = fmaxf(x1p.z + s1.z, 0.f); o1.w = fmaxf(x1p.w + s1.w, 0.f);
        }

        if (t < TT - 1) {
            // write-guard: all group CTAs consumed buffer t&3 (mainloop t-3)
            if (kq == 0) {
                for (;;) {
                    int v = acq_ld(cnsBase + lane);
                    if (__ballot_sync(0xffffffffu, v >= t - 3) == 0xffffffffu)
                        break;
                    __nanosleep(64);
                }
            }
            __syncthreads();

            // write next-step permuted fragments into buffer t&3
            float sv[8] = {o0.x, o0.y, o0.z, o0.w, o1.x, o1.y, o1.z, o1.w};
            unsigned* dh = (unsigned*)&g_Ap[t & 3][(tileE * 128 + gE) * 32];
            unsigned* dl = (unsigned*)&g_Ap[t & 3][(tileE * 128 + 64 + gE) * 32];
            #pragma unroll
            for (int j = 0; j < 4; j++) {
                float v0 = sv[2 * j], v1 = sv[2 * j + 1];
                __nv_bfloat16 h0 = __float2bfloat16(v0);
                __nv_bfloat16 h1 = __float2bfloat16(v1);
                unsigned hw = (unsigned)__bfloat16_as_ushort(h0)
                            | ((unsigned)__bfloat16_as_ushort(h1) << 16);
                __nv_bfloat16 l0 = __float2bfloat16(v0 - __bfloat162float(h0));
                __nv_bfloat16 l1 = __float2bfloat16(v1 - __bfloat162float(h1));
                unsigned lw = (unsigned)__bfloat16_as_ushort(l0)
                            | ((unsigned)__bfloat16_as_ushort(l1) << 16);
                const int L = ((rloc & 7) << 2) + j;
                dh[L * 4 + slot] = hw;
                dl[L * 4 + slot] = lw;
            }

            // publish readiness (threadfenceReduction pattern)
            __syncthreads();
            if (tid == 0) {
                __threadfence();
                rel_st(rdyBase + bn, t);
            }
        }

        // fp32 out-store (not on the cross-CTA critical path)
        *(float4*)po       = o0;
        *(float4*)(po + 4) = o1;
    }
}

// ---------------------------------------------------------------------------
extern "C" void kernel_launch(void* const* d_in, const int* in_sizes, int n_in,
                              void* d_out, int out_size)
{
    const float* x   = (const float*)d_in[0];   // [256,512,512]
    const float* Wxh = (const float*)d_in[1];   // [512,1024]
    const float* bxh = (const float*)d_in[2];   // [1024]
    const float* Whh = (const float*)d_in[3];   // [1024,1024]
    float* out = (float*)d_out;                 // [256,512,1024]

    // Prep: weight splits
    wx_convert<<<(EE * HH) / 256, 256>>>(Wxh);
    wt_convert<<<(HH * HH) / 256, 256>>>(Whh);

    // Phase 1: xh -> d_out (tensor cores, bf16 hi/lo x3)
    const int smem_p1 = 2 * 32768;
    cudaFuncSetAttribute(gemm_xh_mma,
                         cudaFuncAttributeMaxDynamicSharedMemorySize, smem_p1);
    dim3 g1(HH / 128, (BB * TT) / 128);          // (8, 1024)
    gemm_xh_mma<<<g1, 256, smem_p1>>>(x, bxh, out);

    // h0 = relu(xh_0) + permuted fragment split
    init_h0<<<(BB * HH / 2) / 256, 256>>>(out);

    // Phase 2: persistent mma.sync scan (slack-3 dataflow)
    const int smem_p2 = 131072 + 65536;          // W 128KB + partials 64KB
    cudaFuncSetAttribute(rnn_scan_mma,
                         cudaFuncAttributeMaxDynamicSharedMemorySize, smem_p2);
    rnn_scan_mma<<<NCTA, 256, smem_p2>>>(out);

    // reset dataflow flags for next graph replay (stream-ordered)
    flag_reset<<<1, 128>>>();
}

// round 12
// speedup vs baseline: 1.7485x; 1.7485x over previous
#include <cuda_runtime.h>
#include <cuda_bf16.h>

// Problem dims (fixed by the reference)
#define BB   256
#define TT   512
#define EE   512
#define HH   1024
#define LDR  ((long)TT * HH)

#define NCTA 128      // 4 M-tiles (64 rows) x 32 N-tiles (32 cols)

// ---------------------------------------------------------------------------
// Scratch (device globals; no allocation allowed)
// g_Ap[buf][(tile*128 + g)*32 + lane] : hidden state in PRE-PERMUTED mma
//   fragment layout (see round 9 comment).
// ---------------------------------------------------------------------------
__device__ uint4 g_Ap[2][16 * 128 * 32];
__device__ __nv_bfloat16 g_Wkn[2048][HH];
__device__ __nv_bfloat16 g_Wx[1024][HH];

// ---------------------------------------------------------------------------
// PTX helpers
// ---------------------------------------------------------------------------
__device__ __forceinline__ unsigned smem_u32(const void* p) {
    unsigned a;
    asm("{ .reg .u64 t; cvta.to.shared.u64 t, %1; cvt.u32.u64 %0, t; }"
        : "=r"(a) : "l"(p));
    return a;
}

#define LDSM4(r, a) \
    asm volatile("ldmatrix.sync.aligned.m8n8.x4.shared.b16 {%0,%1,%2,%3}, [%4];" \
        : "=r"((r)[0]), "=r"((r)[1]), "=r"((r)[2]), "=r"((r)[3]) : "r"(a))

#define LDSM4T(r, a) \
    asm volatile("ldmatrix.sync.aligned.m8n8.x4.trans.shared.b16 {%0,%1,%2,%3}, [%4];" \
        : "=r"((r)[0]), "=r"((r)[1]), "=r"((r)[2]), "=r"((r)[3]) : "r"(a))

__device__ __forceinline__ void mma16816(float* d, const unsigned* a,
                                         unsigned b0, unsigned b1) {
    asm volatile(
        "mma.sync.aligned.m16n8k16.row.col.f32.bf16.bf16.f32 "
        "{%0,%1,%2,%3}, {%4,%5,%6,%7}, {%8,%9}, {%0,%1,%2,%3};"
        : "+f"(d[0]), "+f"(d[1]), "+f"(d[2]), "+f"(d[3])
        : "r"(a[0]), "r"(a[1]), "r"(a[2]), "r"(a[3]), "r"(b0), "r"(b1));
}

// pack 8 fp32 -> uint4 hi bf16, uint4 lo bf16
__device__ __forceinline__ void split8(float4 a, float4 b, uint4& hi, uint4& lo) {
    float s[8] = {a.x, a.y, a.z, a.w, b.x, b.y, b.z, b.w};
    unsigned h[4], l[4];
    #pragma unroll
    for (int i = 0; i < 4; i++) {
        __nv_bfloat16 h0 = __float2bfloat16(s[2 * i]);
        __nv_bfloat16 h1 = __float2bfloat16(s[2 * i + 1]);
        __nv_bfloat16 l0 = __float2bfloat16(s[2 * i] - __bfloat162float(h0));
        __nv_bfloat16 l1 = __float2bfloat16(s[2 * i + 1] - __bfloat162float(h1));
        h[i] = (unsigned)__bfloat16_as_ushort(h0)
             | ((unsigned)__bfloat16_as_ushort(h1) << 16);
        l[i] = (unsigned)__bfloat16_as_ushort(l0)
             | ((unsigned)__bfloat16_as_ushort(l1) << 16);
    }
    hi = make_uint4(h[0], h[1], h[2], h[3]);
    lo = make_uint4(l[0], l[1], l[2], l[3]);
}

// ---------------------------------------------------------------------------
// Per-bm-group barriers (4 independent groups of 32 CTAs)
// ---------------------------------------------------------------------------
__device__ unsigned int g_bar4[4 * 32];
__global__ void bar_reset() {
    if (threadIdx.x < 128) g_bar4[threadIdx.x] = 0;
}

// ---------------------------------------------------------------------------
// Prep kernels
// ---------------------------------------------------------------------------
__global__ void __launch_bounds__(256)
wt_convert(const float* __restrict__ Whh)
{
    int idx = blockIdx.x * 256 + threadIdx.x;
    int k = idx >> 10, n = idx & 1023;
    float w = Whh[(long)k * HH + n];
    __nv_bfloat16 hi = __float2bfloat16(w);
    __nv_bfloat16 lo = __float2bfloat16(w - __bfloat162float(hi));
    g_Wkn[k][n] = hi;
    g_Wkn[1024 + k][n] = lo;
}

__global__ void __launch_bounds__(256)
wx_convert(const float* __restrict__ Wxh)
{
    int idx = blockIdx.x * 256 + threadIdx.x;
    int k = idx >> 10, n = idx & 1023;
    float w = Wxh[(long)k * HH + n];
    __nv_bfloat16 hi = __float2bfloat16(w);
    __nv_bfloat16 lo = __float2bfloat16(w - __bfloat162float(hi));
    g_Wx[k][n] = hi;
    g_Wx[512 + k][n] = lo;
}

__global__ void __launch_bounds__(256)
init_h0(float* __restrict__ out)
{
    int idx = blockIdx.x * 256 + threadIdx.x;   // 0 .. 128K-1
    int b  = idx >> 9;
    int c2 = (idx & 511) * 2;
    float* p = out + (long)b * LDR + c2;
    float v0 = fmaxf(p[0], 0.f);
    float v1 = fmaxf(p[1], 0.f);
    p[0] = v0; p[1] = v1;

    __nv_bfloat16 h0 = __float2bfloat16(v0);
    __nv_bfloat16 h1 = __float2bfloat16(v1);
    unsigned hw = (unsigned)__bfloat16_as_ushort(h0)
                | ((unsigned)__bfloat16_as_ushort(h1) << 16);
    __nv_bfloat16 l0 = __float2bfloat16(v0 - __bfloat162float(h0));
    __nv_bfloat16 l1 = __float2bfloat16(v1 - __bfloat162float(h1));
    unsigned lw = (unsigned)__bfloat16_as_ushort(l0)
                | ((unsigned)__bfloat16_as_ushort(l1) << 16);

    int tile = b >> 4;
    int rloc = b & 15;
    int g    = c2 >> 4;
    int cb   = c2 & 15;
    int L    = ((rloc & 7) << 2) + ((cb & 7) >> 1);
    int slot = ((rloc & 8) ? 1 : 0) | ((cb & 8) ? 2 : 0);

    unsigned* dh = (unsigned*)&g_Ap[0][(tile * 128 + g) * 32 + L];
    unsigned* dl = (unsigned*)&g_Ap[0][(tile * 128 + 64 + g) * 32 + L];
    dh[slot] = hw;
    dl[slot] = lw;
}

// ---------------------------------------------------------------------------
// Phase 1 (tensor): xh = x @ Wxh + bxh  (unchanged)
// ---------------------------------------------------------------------------
extern __shared__ char smx[];

#define AFX(kg, m) ((unsigned)((kg) * 2048 + ((m) >> 3) * 128 + ((((m) & 7) ^ (kg)) * 16)))

__global__ void __launch_bounds__(256)
gemm_xh_mma(const float* __restrict__ x,
            const float* __restrict__ bias,
            float* __restrict__ C)
{
    const int tid  = threadIdx.x;
    const int wid  = tid >> 5;
    const int lane = tid & 31;
    const int wr   = wid & 3;
    const int wc   = wid >> 2;
    const int bm   = blockIdx.y;
    const int bn   = blockIdx.x;

    const unsigned sb = smem_u32(smx);
    const int q   = lane >> 3;
    const int l7  = lane & 7;
    const int kgq = q >> 1;

    const int am = tid & 127;
    const int wk = tid & 31;

    float2 breg[8];
    #pragma unroll
    for (int n8 = 0; n8 < 8; n8++)
        breg[n8] = *(const float2*)&bias[bn * 128 + wc * 64 + n8 * 8 + (lane & 3) * 2];

    float acc[2][8][4];
    #pragma unroll
    for (int m = 0; m < 2; m++)
        #pragma unroll
        for (int n = 0; n < 8; n++)
            #pragma unroll
            for (int j = 0; j < 4; j++) acc[m][n][j] = 0.f;

    const float* xb = x + (long)(bm * 128) * EE;

    float4 xa[2][2];
    uint4  wvh[2], wvl[2];
    #pragma unroll
    for (int i = 0; i < 2; i++) {
        int idx = tid + i * 256;
        int kg = idx >> 7;
        const float* p = xb + (long)am * EE + kg * 8;
        xa[i][0] = *(const float4*)p;
        xa[i][1] = *(const float4*)(p + 4);
        int pp = (idx >> 5) & 15;
        wvh[i] = *(const uint4*)&g_Wx[wk][bn * 128 + pp * 8];
        wvl[i] = *(const uint4*)&g_Wx[512 + wk][bn * 128 + pp * 8];
    }
    #pragma unroll
    for (int i = 0; i < 2; i++) {
        int idx = tid + i * 256;
        int kg = idx >> 7;
        uint4 hi, lo;
        split8(xa[i][0], xa[i][1], hi, lo);
        unsigned ao = AFX(kg, am);
        *(uint4*)(smx + ao)         = hi;
        *(uint4*)(smx + 8192 + ao)  = lo;
        int pp = (idx >> 5) & 15;
        unsigned wo = 16384u + (unsigned)pp * 512u + (unsigned)wk * 16u;
        *(uint4*)(smx + wo)         = wvh[i];
        *(uint4*)(smx + 8192 + wo)  = wvl[i];
    }
    __syncthreads();

    unsigned buf = 0;
    for (int kc = 0; kc < 16; kc++) {
        const bool more = (kc + 1 < 16);
        if (more) {
            const int k0 = (kc + 1) * 32;
            #pragma unroll
            for (int i = 0; i < 2; i++) {
                int idx = tid + i * 256;
                int kg = idx >> 7;
                const float* p = xb + (long)am * EE + k0 + kg * 8;
                xa[i][0] = *(const float4*)p;
                xa[i][1] = *(const float4*)(p + 4);
                int pp = (idx >> 5) & 15;
                wvh[i] = *(const uint4*)&g_Wx[k0 + wk][bn * 128 + pp * 8];
                wvl[i] = *(const uint4*)&g_Wx[512 + k0 + wk][bn * 128 + pp * 8];
            }
        }

        const unsigned B0 = sb + buf * 32768u;
        #pragma unroll
        for (int s16 = 0; s16 < 2; s16++) {
            const int kg = s16 * 2 + kgq;
            const unsigned aoff = (unsigned)kg * 2048u + (unsigned)((l7 ^ kg) * 16);
            unsigned ahi[2][4], alo[2][4];
            LDSM4(ahi[0], B0 + aoff + (unsigned)(wr * 4 + 0 + (q & 1)) * 128u);
            LDSM4(ahi[1], B0 + aoff + (unsigned)(wr * 4 + 2 + (q & 1)) * 128u);
            LDSM4(alo[0], B0 + 8192u + aoff + (unsigned)(wr * 4 + 0 + (q & 1)) * 128u);
            LDSM4(alo[1], B0 + 8192u + aoff + (unsigned)(wr * 4 + 2 + (q & 1)) * 128u);

            const unsigned wrow = (unsigned)(s16 * 16 + (q & 1) * 8 + l7) * 16u;
            #pragma unroll
            for (int pp = 0; pp < 4; pp++) {
                unsigned wh[4], wl[4];
                unsigned wbase = B0 + 16384u
                               + (unsigned)(wc * 8 + pp * 2 + kgq) * 512u + wrow;
                LDSM4T(wh, wbase);
                LDSM4T(wl, wbase + 8192u);
                const int n0 = pp * 2, n1 = pp * 2 + 1;
                mma16816(acc[0][n0], ahi[0], wh[0], wh[1]);
                mma16816(acc[0][n1], ahi[0], wh[2], wh[3]);
                mma16816(acc[1][n0], ahi[1], wh[0], wh[1]);
                mma16816(acc[1][n1], ahi[1], wh[2], wh[3]);
                mma16816(acc[0][n0], alo[0], wh[0], wh[1]);
                mma16816(acc[0][n1], alo[0], wh[2], wh[3]);
                mma16816(acc[1][n0], alo[1], wh[0], wh[1]);
                mma16816(acc[1][n1], alo[1], wh[2], wh[3]);
                mma16816(acc[0][n0], ahi[0], wl[0], wl[1]);
                mma16816(acc[0][n1], ahi[0], wl[2], wl[3]);
                mma16816(acc[1][n0], ahi[1], wl[0], wl[1]);
                mma16816(acc[1][n1], ahi[1], wl[2], wl[3]);
            }
        }

        if (more) {
            const unsigned nb = (buf ^ 1u) * 32768u;
            #pragma unroll
            for (int i = 0; i < 2; i++) {
                int idx = tid + i * 256;
                int kg = idx >> 7;
                uint4 hi, lo;
                split8(xa[i][0], xa[i][1], hi, lo);
                unsigned ao = nb + AFX(kg, am);
                *(uint4*)(smx + ao)        = hi;
                *(uint4*)(smx + 8192 + ao) = lo;
                int pp = (idx >> 5) & 15;
                unsigned wo = nb + 16384u + (unsigned)pp * 512u + (unsigned)wk * 16u;
                *(uint4*)(smx + wo)        = wvh[i];
                *(uint4*)(smx + 8192 + wo) = wvl[i];
            }
            __syncthreads();
            buf ^= 1u;
        }
    }

    #pragma unroll
    for (int mm = 0; mm < 2; mm++) {
        #pragma unroll
        for (int half = 0; half < 2; half++) {
            long row = (long)bm * 128 + wr * 32 + mm * 16 + (lane >> 2) + half * 8;
            float* pr = C + row * HH + bn * 128 + wc * 64 + (lane & 3) * 2;
            #pragma unroll
            for (int n8 = 0; n8 < 8; n8++) {
                float2 o;
                o.x = acc[mm][n8][half * 2 + 0] + breg[n8].x;
                o.y = acc[mm][n8][half * 2 + 1] + breg[n8].y;
                *(float2*)(pr + n8 * 8) = o;
            }
        }
    }
}

// ---------------------------------------------------------------------------
// Phase 2: persistent mma.sync scan — fragment-resident state, 512 threads.
// 16 warps = 2 m-halves (wm: 32 rows) x 8 granule owners (kq). Warp (wm,kq):
// triple {AhiWhi, AhiWlo, AloWhi} at m32 x n32 for granules gk = i*8+kq.
// 4 warps/SMSP hides LDSM/LDG/store phases under MMA issue. Round-10 sync:
// per-bm 32-CTA barrier, early arrive, xh prefetch.
// ---------------------------------------------------------------------------
__global__ void __launch_bounds__(512, 1)
rnn_scan_mma(float* __restrict__ out)
{
    const int tid  = threadIdx.x;
    const int wid  = tid >> 5;
    const int kq   = wid & 7;           // granule owner 0..7
    const int wm   = wid >> 3;          // m-half 0..1
    const int lane = tid & 31;
    const int bm   = blockIdx.x >> 5;
    const int bn   = blockIdx.x & 31;

    const unsigned sb = smem_u32(smx);

    // ---- stage W slice into SMEM panels (once): hi @0, lo @65536 ----
    for (int i = 0; i < 16; i++) {
        int kk = i * 128 + (tid >> 2);     // 0..2047 packed k
        int p  = tid & 3;                  // n8 panel
        uint4 v = *(const uint4*)&g_Wkn[kk][bn * 32 + p * 8];
        unsigned off = (unsigned)(kk >> 10) * 65536u
                     + (unsigned)p * 16384u + (unsigned)(kk & 1023) * 16u;
        *(uint4*)(smx + off) = v;
    }
    __syncthreads();

    // W ldmatrix lane addressing
    const int q   = lane >> 3;
    const int l7  = lane & 7;
    const int kgq = q >> 1;
    const unsigned wrowsel = (unsigned)((q & 1) * 8 + l7) * 16u;
    const unsigned whiBase = sb + (unsigned)kgq * 16384u + wrowsel;
    const unsigned wloBase = whiBase + 65536u;

    // partial-store mapping
    const int eg = lane >> 2;           // 0..7
    const int ei = lane & 3;            // 0..3
    // reduction / epilogue mapping (512 threads: 64 rows x 8 col-quads)
    const int r64 = tid >> 3;           // 0..63
    const int n0  = (tid & 7) * 4;      // 0,4,...,28

    const int bm4 = bm * 4;
    unsigned* const barp = &g_bar4[bm * 32];
    unsigned nbar = 0;

    // epilogue constants
    const int gb    = bm * 64 + r64;
    const int tileE = gb >> 4;
    const int rloc  = gb & 15;
    const int Cb    = bn * 32 + n0;
    const int gE    = Cb >> 4;
    const int slot  = ((rloc & 8) ? 1 : 0) | ((Cb & 8) ? 2 : 0);
    const int L0    = ((rloc & 7) << 2) + ((n0 & 7) >> 1);
    // reduction row constants
    const int wmE = r64 >> 5;
    const int rl  = r64 & 31;

    for (int t = 1; t < TT; t++) {
        const uint4* Ab = &g_Ap[(t + 1) & 1][0];

        // prefetch the xh quad for this step (h-independent; hides DRAM)
        float* po = out + (long)gb * LDR + (long)t * HH + Cb;
        float4 x0p = *(const float4*)po;

        float d[2][4][4];                // [mi][n8][frag]
        #pragma unroll
        for (int mi = 0; mi < 2; mi++)
            #pragma unroll
            for (int nt = 0; nt < 4; nt++)
                #pragma unroll
                for (int j = 0; j < 4; j++) d[mi][nt][j] = 0.f;

        uint4 cur[4], nxt[4];

        // prefetch granule-set 0 (gk = kq): hi + lo frags for 2 m-tiles
        #pragma unroll
        for (int mi = 0; mi < 2; mi++) {
            const int tl = bm4 + wm * 2 + mi;
            cur[mi * 2 + 0] = Ab[(tl * 128 + kq) * 32 + lane];
            cur[mi * 2 + 1] = Ab[(tl * 128 + 64 + kq) * 32 + lane];
        }

        #pragma unroll
        for (int i = 0; i < 8; i++) {
            if (i < 7) {
                const int gk1 = (i + 1) * 8 + kq;
                #pragma unroll
                for (int mi = 0; mi < 2; mi++) {
                    const int tl = bm4 + wm * 2 + mi;
                    nxt[mi * 2 + 0] = Ab[(tl * 128 + gk1) * 32 + lane];
                    nxt[mi * 2 + 1] = Ab[(tl * 128 + 64 + gk1) * 32 + lane];
                }
            }

            const int gk = i * 8 + kq;
            const unsigned wko = (unsigned)gk * 256u;
            unsigned wh1[4], wh2[4], wl1[4], wl2[4];
            LDSM4T(wh1, whiBase + wko);
            LDSM4T(wh2, whiBase + 32768u + wko);
            LDSM4T(wl1, wloBase + wko);
            LDSM4T(wl2, wloBase + 32768u + wko);

            #pragma unroll
            for (int mi = 0; mi < 2; mi++) {
                const unsigned* ahi = (const unsigned*)&cur[mi * 2 + 0];
                const unsigned* alo = (const unsigned*)&cur[mi * 2 + 1];
                mma16816(d[mi][0], ahi, wh1[0], wh1[1]);
                mma16816(d[mi][1], ahi, wh1[2], wh1[3]);
                mma16816(d[mi][2], ahi, wh2[0], wh2[1]);
                mma16816(d[mi][3], ahi, wh2[2], wh2[3]);
                mma16816(d[mi][0], ahi, wl1[0], wl1[1]);
                mma16816(d[mi][1], ahi, wl1[2], wl1[3]);
                mma16816(d[mi][2], ahi, wl2[0], wl2[1]);
                mma16816(d[mi][3], ahi, wl2[2], wl2[3]);
                mma16816(d[mi][0], alo, wh1[0], wh1[1]);
                mma16816(d[mi][1], alo, wh1[2], wh1[3]);
                mma16816(d[mi][2], alo, wh2[0], wh2[1]);
                mma16816(d[mi][3], alo, wh2[2], wh2[3]);
            }

            if (i < 7) {
                #pragma unroll
                for (int j = 0; j < 4; j++) cur[j] = nxt[j];
            }
        }

        // ---- store m32xn32 fp32 partial (XOR-16 swizzle on rows) @128KB ----
        {
            const unsigned pb = 131072u + (unsigned)((wm * 8 + kq) * 4096);
            #pragma unroll
            for (int mi = 0; mi < 2; mi++) {
                #pragma unroll
                for (int half = 0; half < 2; half++) {
                    const int r = mi * 16 + eg + half * 8;   // 0..31
                    const unsigned xr = (unsigned)((r & 7) * 16);
                    #pragma unroll
                    for (int nt = 0; nt < 4; nt++) {
                        float2 pv;
                        pv.x = d[mi][nt][half * 2 + 0];
                        pv.y = d[mi][nt][half * 2 + 1];
                        unsigned cb = (unsigned)(nt * 32 + ei * 8) ^ xr;
                        *(float2*)(smx + pb + (unsigned)r * 128u + cb) = pv;
                    }
                }
            }
        }
        __syncthreads();

        // ---- reduce 8 partials + fused epilogue ----
        float4 o0;
        {
            const unsigned xr = (unsigned)((rl & 7) * 16);
            const unsigned c0 = ((unsigned)(n0 * 4)) ^ xr;
            float4 s0 = {0.f, 0.f, 0.f, 0.f};
            #pragma unroll
            for (int p = 0; p < 8; p++) {
                const char* pp = smx + 131072u + (unsigned)((wmE * 8 + p) * 4096)
                               + (unsigned)rl * 128u;
                float4 a = *(const float4*)(pp + c0);
                s0.x += a.x; s0.y += a.y; s0.z += a.z; s0.w += a.w;
            }

            o0.x = fmaxf(x0p.x + s0.x, 0.f);
            o0.y = fmaxf(x0p.y + s0.y, 0.f);
            o0.z = fmaxf(x0p.z + s0.z, 0.f);
            o0.w = fmaxf(x0p.w + s0.w, 0.f);

            // write next-step permuted fragments FIRST (the cross-CTA dep)
            float sv[4] = {o0.x, o0.y, o0.z, o0.w};
            unsigned* dh = (unsigned*)&g_Ap[t & 1][(tileE * 128 + gE) * 32];
            unsigned* dl = (unsigned*)&g_Ap[t & 1][(tileE * 128 + 64 + gE) * 32];
            #pragma unroll
            for (int j = 0; j < 2; j++) {
                float v0 = sv[2 * j], v1 = sv[2 * j + 1];
                __nv_bfloat16 h0 = __float2bfloat16(v0);
                __nv_bfloat16 h1 = __float2bfloat16(v1);
                unsigned hw = (unsigned)__bfloat16_as_ushort(h0)
                            | ((unsigned)__bfloat16_as_ushort(h1) << 16);
                __nv_bfloat16 l0 = __float2bfloat16(v0 - __bfloat162float(h0));
                __nv_bfloat16 l1 = __float2bfloat16(v1 - __bfloat162float(h1));
                unsigned lw = (unsigned)__bfloat16_as_ushort(l0)
                            | ((unsigned)__bfloat16_as_ushort(l1) << 16);
                dh[(L0 + j) * 4 + slot] = hw;
                dl[(L0 + j) * 4 + slot] = lw;
            }
        }

        if (t < TT - 1) {
            nbar++;
            // arrive early: fragments published; overlap out-store with
            // other CTAs' arrival.
            __syncthreads();
            if (tid == 0) {
                __threadfence();
                atomicAdd(barp, 1u);
            }
            *(float4*)po = o0;
            if (tid == 0) {
                volatile unsigned* p = barp;
                const unsigned tgt = nbar * 32u;
                while (*p < tgt) __nanosleep(32);
                __threadfence();
            }
            __syncthreads();
        } else {
            *(float4*)po = o0;
        }
    }
}

// ---------------------------------------------------------------------------
extern "C" void kernel_launch(void* const* d_in, const int* in_sizes, int n_in,
                              void* d_out, int out_size)
{
    const float* x   = (const float*)d_in[0];
    const float* Wxh = (const float*)d_in[1];
    const float* bxh = (const float*)d_in[2];
    const float* Whh = (const float*)d_in[3];
    float* out = (float*)d_out;

    wx_convert<<<(EE * HH) / 256, 256>>>(Wxh);
    wt_convert<<<(HH * HH) / 256, 256>>>(Whh);

    const int smem_p1 = 2 * 32768;
    cudaFuncSetAttribute(gemm_xh_mma,
                         cudaFuncAttributeMaxDynamicSharedMemorySize, smem_p1);
    dim3 g1(HH / 128, (BB * TT) / 128);
    gemm_xh_mma<<<g1, 256, smem_p1>>>(x, bxh, out);

    init_h0<<<(BB * HH / 2) / 256, 256>>>(out);

    const int smem_p2 = 131072 + 65536;
    cudaFuncSetAttribute(rnn_scan_mma,
                         cudaFuncAttributeMaxDynamicSharedMemorySize, smem_p2);
    rnn_scan_mma<<<NCTA, 512, smem_p2>>>(out);

    bar_reset<<<1, 128>>>();
}

// round 13
// speedup vs baseline: 1.8198x; 1.0408x over previous
#include <cuda_runtime.h>
#include <cuda_bf16.h>

// Problem dims (fixed by the reference)
#define BB   256
#define TT   512
#define EE   512
#define HH   1024
#define LDR  ((long)TT * HH)

#define NCTA 128      // 4 M-tiles (64 rows) x 32 N-tiles (32 cols)

// ---------------------------------------------------------------------------
// Scratch (device globals; no allocation allowed)
// g_Ap[buf][(tile*128 + g)*32 + lane] : hidden state in PRE-PERMUTED mma
//   fragment layout (see round 9 comment).
// ---------------------------------------------------------------------------
__device__ uint4 g_Ap[2][16 * 128 * 32];
__device__ __nv_bfloat16 g_Wkn[2048][HH];
__device__ __nv_bfloat16 g_Wx[1024][HH];

// ---------------------------------------------------------------------------
// PTX helpers
// ---------------------------------------------------------------------------
__device__ __forceinline__ unsigned smem_u32(const void* p) {
    unsigned a;
    asm("{ .reg .u64 t; cvta.to.shared.u64 t, %1; cvt.u32.u64 %0, t; }"
        : "=r"(a) : "l"(p));
    return a;
}

__device__ __forceinline__ unsigned acq_ldu(const unsigned* p) {
    unsigned v;
    asm volatile("ld.acquire.gpu.global.b32 %0, [%1];" : "=r"(v) : "l"(p));
    return v;
}

#define LDSM4(r, a) \
    asm volatile("ldmatrix.sync.aligned.m8n8.x4.shared.b16 {%0,%1,%2,%3}, [%4];" \
        : "=r"((r)[0]), "=r"((r)[1]), "=r"((r)[2]), "=r"((r)[3]) : "r"(a))

#define LDSM4T(r, a) \
    asm volatile("ldmatrix.sync.aligned.m8n8.x4.trans.shared.b16 {%0,%1,%2,%3}, [%4];" \
        : "=r"((r)[0]), "=r"((r)[1]), "=r"((r)[2]), "=r"((r)[3]) : "r"(a))

__device__ __forceinline__ void mma16816(float* d, const unsigned* a,
                                         unsigned b0, unsigned b1) {
    asm volatile(
        "mma.sync.aligned.m16n8k16.row.col.f32.bf16.bf16.f32 "
        "{%0,%1,%2,%3}, {%4,%5,%6,%7}, {%8,%9}, {%0,%1,%2,%3};"
        : "+f"(d[0]), "+f"(d[1]), "+f"(d[2]), "+f"(d[3])
        : "r"(a[0]), "r"(a[1]), "r"(a[2]), "r"(a[3]), "r"(b0), "r"(b1));
}

// pack 8 fp32 -> uint4 hi bf16, uint4 lo bf16
__device__ __forceinline__ void split8(float4 a, float4 b, uint4& hi, uint4& lo) {
    float s[8] = {a.x, a.y, a.z, a.w, b.x, b.y, b.z, b.w};
    unsigned h[4], l[4];
    #pragma unroll
    for (int i = 0; i < 4; i++) {
        __nv_bfloat16 h0 = __float2bfloat16(s[2 * i]);
        __nv_bfloat16 h1 = __float2bfloat16(s[2 * i + 1]);
        __nv_bfloat16 l0 = __float2bfloat16(s[2 * i] - __bfloat162float(h0));
        __nv_bfloat16 l1 = __float2bfloat16(s[2 * i + 1] - __bfloat162float(h1));
        h[i] = (unsigned)__bfloat16_as_ushort(h0)
             | ((unsigned)__bfloat16_as_ushort(h1) << 16);
        l[i] = (unsigned)__bfloat16_as_ushort(l0)
             | ((unsigned)__bfloat16_as_ushort(l1) << 16);
    }
    hi = make_uint4(h[0], h[1], h[2], h[3]);
    lo = make_uint4(l[0], l[1], l[2], l[3]);
}

// ---------------------------------------------------------------------------
// Per-bm-group barrier counters (4 independent groups of 32 CTAs), padded
// ---------------------------------------------------------------------------
__device__ unsigned int g_bar4[4 * 32];
__global__ void bar_reset() {
    if (threadIdx.x < 128) g_bar4[threadIdx.x] = 0;
}

// ---------------------------------------------------------------------------
// Prep kernels
// ---------------------------------------------------------------------------
__global__ void __launch_bounds__(256)
wt_convert(const float* __restrict__ Whh)
{
    int idx = blockIdx.x * 256 + threadIdx.x;
    int k = idx >> 10, n = idx & 1023;
    float w = Whh[(long)k * HH + n];
    __nv_bfloat16 hi = __float2bfloat16(w);
    __nv_bfloat16 lo = __float2bfloat16(w - __bfloat162float(hi));
    g_Wkn[k][n] = hi;
    g_Wkn[1024 + k][n] = lo;
}

__global__ void __launch_bounds__(256)
wx_convert(const float* __restrict__ Wxh)
{
    int idx = blockIdx.x * 256 + threadIdx.x;
    int k = idx >> 10, n = idx & 1023;
    float w = Wxh[(long)k * HH + n];
    __nv_bfloat16 hi = __float2bfloat16(w);
    __nv_bfloat16 lo = __float2bfloat16(w - __bfloat162float(hi));
    g_Wx[k][n] = hi;
    g_Wx[512 + k][n] = lo;
}

__global__ void __launch_bounds__(256)
init_h0(float* __restrict__ out)
{
    int idx = blockIdx.x * 256 + threadIdx.x;   // 0 .. 128K-1
    int b  = idx >> 9;
    int c2 = (idx & 511) * 2;
    float* p = out + (long)b * LDR + c2;
    float v0 = fmaxf(p[0], 0.f);
    float v1 = fmaxf(p[1], 0.f);
    p[0] = v0; p[1] = v1;

    __nv_bfloat16 h0 = __float2bfloat16(v0);
    __nv_bfloat16 h1 = __float2bfloat16(v1);
    unsigned hw = (unsigned)__bfloat16_as_ushort(h0)
                | ((unsigned)__bfloat16_as_ushort(h1) << 16);
    __nv_bfloat16 l0 = __float2bfloat16(v0 - __bfloat162float(h0));
    __nv_bfloat16 l1 = __float2bfloat16(v1 - __bfloat162float(h1));
    unsigned lw = (unsigned)__bfloat16_as_ushort(l0)
                | ((unsigned)__bfloat16_as_ushort(l1) << 16);

    int tile = b >> 4;
    int rloc = b & 15;
    int g    = c2 >> 4;
    int cb   = c2 & 15;
    int L    = ((rloc & 7) << 2) + ((cb & 7) >> 1);
    int slot = ((rloc & 8) ? 1 : 0) | ((cb & 8) ? 2 : 0);

    unsigned* dh = (unsigned*)&g_Ap[0][(tile * 128 + g) * 32 + L];
    unsigned* dl = (unsigned*)&g_Ap[0][(tile * 128 + 64 + g) * 32 + L];
    dh[slot] = hw;
    dl[slot] = lw;
}

// ---------------------------------------------------------------------------
// Phase 1 (tensor): xh = x @ Wxh + bxh  (unchanged; at HMMA roofline)
// ---------------------------------------------------------------------------
extern __shared__ char smx[];

#define AFX(kg, m) ((unsigned)((kg) * 2048 + ((m) >> 3) * 128 + ((((m) & 7) ^ (kg)) * 16)))

__global__ void __launch_bounds__(256)
gemm_xh_mma(const float* __restrict__ x,
            const float* __restrict__ bias,
            float* __restrict__ C)
{
    const int tid  = threadIdx.x;
    const int wid  = tid >> 5;
    const int lane = tid & 31;
    const int wr   = wid & 3;
    const int wc   = wid >> 2;
    const int bm   = blockIdx.y;
    const int bn   = blockIdx.x;

    const unsigned sb = smem_u32(smx);
    const int q   = lane >> 3;
    const int l7  = lane & 7;
    const int kgq = q >> 1;

    const int am = tid & 127;
    const int wk = tid & 31;

    float2 breg[8];
    #pragma unroll
    for (int n8 = 0; n8 < 8; n8++)
        breg[n8] = *(const float2*)&bias[bn * 128 + wc * 64 + n8 * 8 + (lane & 3) * 2];

    float acc[2][8][4];
    #pragma unroll
    for (int m = 0; m < 2; m++)
        #pragma unroll
        for (int n = 0; n < 8; n++)
            #pragma unroll
            for (int j = 0; j < 4; j++) acc[m][n][j] = 0.f;

    const float* xb = x + (long)(bm * 128) * EE;

    float4 xa[2][2];
    uint4  wvh[2], wvl[2];
    #pragma unroll
    for (int i = 0; i < 2; i++) {
        int idx = tid + i * 256;
        int kg = idx >> 7;
        const float* p = xb + (long)am * EE + kg * 8;
        xa[i][0] = *(const float4*)p;
        xa[i][1] = *(const float4*)(p + 4);
        int pp = (idx >> 5) & 15;
        wvh[i] = *(const uint4*)&g_Wx[wk][bn * 128 + pp * 8];
        wvl[i] = *(const uint4*)&g_Wx[512 + wk][bn * 128 + pp * 8];
    }
    #pragma unroll
    for (int i = 0; i < 2; i++) {
        int idx = tid + i * 256;
        int kg = idx >> 7;
        uint4 hi, lo;
        split8(xa[i][0], xa[i][1], hi, lo);
        unsigned ao = AFX(kg, am);
        *(uint4*)(smx + ao)         = hi;
        *(uint4*)(smx + 8192 + ao)  = lo;
        int pp = (idx >> 5) & 15;
        unsigned wo = 16384u + (unsigned)pp * 512u + (unsigned)wk * 16u;
        *(uint4*)(smx + wo)         = wvh[i];
        *(uint4*)(smx + 8192 + wo)  = wvl[i];
    }
    __syncthreads();

    unsigned buf = 0;
    for (int kc = 0; kc < 16; kc++) {
        const bool more = (kc + 1 < 16);
        if (more) {
            const int k0 = (kc + 1) * 32;
            #pragma unroll
            for (int i = 0; i < 2; i++) {
                int idx = tid + i * 256;
                int kg = idx >> 7;
                const float* p = xb + (long)am * EE + k0 + kg * 8;
                xa[i][0] = *(const float4*)p;
                xa[i][1] = *(const float4*)(p + 4);
                int pp = (idx >> 5) & 15;
                wvh[i] = *(const uint4*)&g_Wx[k0 + wk][bn * 128 + pp * 8];
                wvl[i] = *(const uint4*)&g_Wx[512 + k0 + wk][bn * 128 + pp * 8];
            }
        }

        const unsigned B0 = sb + buf * 32768u;
        #pragma unroll
        for (int s16 = 0; s16 < 2; s16++) {
            const int kg = s16 * 2 + kgq;
            const unsigned aoff = (unsigned)kg * 2048u + (unsigned)((l7 ^ kg) * 16);
            unsigned ahi[2][4], alo[2][4];
            LDSM4(ahi[0], B0 + aoff + (unsigned)(wr * 4 + 0 + (q & 1)) * 128u);
            LDSM4(ahi[1], B0 + aoff + (unsigned)(wr * 4 + 2 + (q & 1)) * 128u);
            LDSM4(alo[0], B0 + 8192u + aoff + (unsigned)(wr * 4 + 0 + (q & 1)) * 128u);
            LDSM4(alo[1], B0 + 8192u + aoff + (unsigned)(wr * 4 + 2 + (q & 1)) * 128u);

            const unsigned wrow = (unsigned)(s16 * 16 + (q & 1) * 8 + l7) * 16u;
            #pragma unroll
            for (int pp = 0; pp < 4; pp++) {
                unsigned wh[4], wl[4];
                unsigned wbase = B0 + 16384u
                               + (unsigned)(wc * 8 + pp * 2 + kgq) * 512u + wrow;
                LDSM4T(wh, wbase);
                LDSM4T(wl, wbase + 8192u);
                const int n0 = pp * 2, n1 = pp * 2 + 1;
                mma16816(acc[0][n0], ahi[0], wh[0], wh[1]);
                mma16816(acc[0][n1], ahi[0], wh[2], wh[3]);
                mma16816(acc[1][n0], ahi[1], wh[0], wh[1]);
                mma16816(acc[1][n1], ahi[1], wh[2], wh[3]);
                mma16816(acc[0][n0], alo[0], wh[0], wh[1]);
                mma16816(acc[0][n1], alo[0], wh[2], wh[3]);
                mma16816(acc[1][n0], alo[1], wh[0], wh[1]);
                mma16816(acc[1][n1], alo[1], wh[2], wh[3]);
                mma16816(acc[0][n0], ahi[0], wl[0], wl[1]);
                mma16816(acc[0][n1], ahi[0], wl[2], wl[3]);
                mma16816(acc[1][n0], ahi[1], wl[0], wl[1]);
                mma16816(acc[1][n1], ahi[1], wl[2], wl[3]);
            }
        }

        if (more) {
            const unsigned nb = (buf ^ 1u) * 32768u;
            #pragma unroll
            for (int i = 0; i < 2; i++) {
                int idx = tid + i * 256;
                int kg = idx >> 7;
                uint4 hi, lo;
                split8(xa[i][0], xa[i][1], hi, lo);
                unsigned ao = nb + AFX(kg, am);
                *(uint4*)(smx + ao)        = hi;
                *(uint4*)(smx + 8192 + ao) = lo;
                int pp = (idx >> 5) & 15;
                unsigned wo = nb + 16384u + (unsigned)pp * 512u + (unsigned)wk * 16u;
                *(uint4*)(smx + wo)        = wvh[i];
                *(uint4*)(smx + 8192 + wo) = wvl[i];
            }
            __syncthreads();
            buf ^= 1u;
        }
    }

    #pragma unroll
    for (int mm = 0; mm < 2; mm++) {
        #pragma unroll
        for (int half = 0; half < 2; half++) {
            long row = (long)bm * 128 + wr * 32 + mm * 16 + (lane >> 2) + half * 8;
            float* pr = C + row * HH + bn * 128 + wc * 64 + (lane & 3) * 2;
            #pragma unroll
            for (int n8 = 0; n8 < 8; n8++) {
                float2 o;
                o.x = acc[mm][n8][half * 2 + 0] + breg[n8].x;
                o.y = acc[mm][n8][half * 2 + 1] + breg[n8].y;
                *(float2*)(pr + n8 * 8) = o;
            }
        }
    }
}

// ---------------------------------------------------------------------------
// Phase 2: persistent mma.sync scan — fragment-resident state, 512 threads,
// warp-autonomous barrier waits. Per step: warps individually wait for the
// group counter >= 32*(t-1) just before their A-fragment loads (xh prefetch
// and W-set0 LDSM hoisted above the wait); 2 CTA-wide syncs per step
// (post-partials, pre-arrive); arrive by tid0 doesn't block other warps.
// ---------------------------------------------------------------------------
__global__ void __launch_bounds__(512, 1)
rnn_scan_mma(float* __restrict__ out)
{
    const int tid  = threadIdx.x;
    const int wid  = tid >> 5;
    const int kq   = wid & 7;           // granule owner 0..7
    const int wm   = wid >> 3;          // m-half 0..1
    const int lane = tid & 31;
    const int bm   = blockIdx.x >> 5;
    const int bn   = blockIdx.x & 31;

    const unsigned sb = smem_u32(smx);

    // ---- stage W slice into SMEM panels (once): hi @0, lo @65536 ----
    for (int i = 0; i < 16; i++) {
        int kk = i * 128 + (tid >> 2);
        int p  = tid & 3;
        uint4 v = *(const uint4*)&g_Wkn[kk][bn * 32 + p * 8];
        unsigned off = (unsigned)(kk >> 10) * 65536u
                     + (unsigned)p * 16384u + (unsigned)(kk & 1023) * 16u;
        *(uint4*)(smx + off) = v;
    }
    __syncthreads();

    // W ldmatrix lane addressing
    const int q   = lane >> 3;
    const int l7  = lane & 7;
    const int kgq = q >> 1;
    const unsigned wrowsel = (unsigned)((q & 1) * 8 + l7) * 16u;
    const unsigned whiBase = sb + (unsigned)kgq * 16384u + wrowsel;
    const unsigned wloBase = whiBase + 65536u;

    // partial-store mapping
    const int eg = lane >> 2;
    const int ei = lane & 3;
    // reduction / epilogue mapping (512 threads: 64 rows x 8 col-quads)
    const int r64 = tid >> 3;
    const int n0  = (tid & 7) * 4;

    const int bm4 = bm * 4;
    unsigned* const barp = &g_bar4[bm * 32];

    // epilogue constants
    const int gb    = bm * 64 + r64;
    const int tileE = gb >> 4;
    const int rloc  = gb & 15;
    const int Cb    = bn * 32 + n0;
    const int gE    = Cb >> 4;
    const int slot  = ((rloc & 8) ? 1 : 0) | ((Cb & 8) ? 2 : 0);
    const int L0    = ((rloc & 7) << 2) + ((n0 & 7) >> 1);
    const int wmE = r64 >> 5;
    const int rl  = r64 & 31;

    for (int t = 1; t < TT; t++) {
        const uint4* Ab = &g_Ap[(t + 1) & 1][0];

        // ---- pre-wait prologue (independent of producers) ----
        float* po = out + (long)gb * LDR + (long)t * HH + Cb;
        float4 x0p = *(const float4*)po;

        // W fragments for granule-set 0 (smem, producer-independent)
        unsigned wh1[4], wh2[4], wl1[4], wl2[4];
        {
            const unsigned wko0 = (unsigned)kq * 256u;
            LDSM4T(wh1, whiBase + wko0);
            LDSM4T(wh2, whiBase + 32768u + wko0);
            LDSM4T(wl1, wloBase + wko0);
            LDSM4T(wl2, wloBase + 32768u + wko0);
        }

        float d[2][4][4];
        #pragma unroll
        for (int mi = 0; mi < 2; mi++)
            #pragma unroll
            for (int nt = 0; nt < 4; nt++)
                #pragma unroll
                for (int j = 0; j < 4; j++) d[mi][nt][j] = 0.f;

        // ---- warp-autonomous wait: producers published step t-1 ----
        if (t > 1) {
            const unsigned tgt = (unsigned)(t - 1) * 32u;
            while (acq_ldu(barp) < tgt) __nanosleep(32);
            __syncwarp();
        }

        uint4 cur[4], nxt[4];
        #pragma unroll
        for (int mi = 0; mi < 2; mi++) {
            const int tl = bm4 + wm * 2 + mi;
            cur[mi * 2 + 0] = Ab[(tl * 128 + kq) * 32 + lane];
            cur[mi * 2 + 1] = Ab[(tl * 128 + 64 + kq) * 32 + lane];
        }

        #pragma unroll
        for (int i = 0; i < 8; i++) {
            if (i < 7) {
                const int gk1 = (i + 1) * 8 + kq;
                #pragma unroll
                for (int mi = 0; mi < 2; mi++) {
                    const int tl = bm4 + wm * 2 + mi;
                    nxt[mi * 2 + 0] = Ab[(tl * 128 + gk1) * 32 + lane];
                    nxt[mi * 2 + 1] = Ab[(tl * 128 + 64 + gk1) * 32 + lane];
                }
            }

            #pragma unroll
            for (int mi = 0; mi < 2; mi++) {
                const unsigned* ahi = (const unsigned*)&cur[mi * 2 + 0];
                const unsigned* alo = (const unsigned*)&cur[mi * 2 + 1];
                mma16816(d[mi][0], ahi, wh1[0], wh1[1]);
                mma16816(d[mi][1], ahi, wh1[2], wh1[3]);
                mma16816(d[mi][2], ahi, wh2[0], wh2[1]);
                mma16816(d[mi][3], ahi, wh2[2], wh2[3]);
                mma16816(d[mi][0], ahi, wl1[0], wl1[1]);
                mma16816(d[mi][1], ahi, wl1[2], wl1[3]);
                mma16816(d[mi][2], ahi, wl2[0], wl2[1]);
                mma16816(d[mi][3], ahi, wl2[2], wl2[3]);
                mma16816(d[mi][0], alo, wh1[0], wh1[1]);
                mma16816(d[mi][1], alo, wh1[2], wh1[3]);
                mma16816(d[mi][2], alo, wh2[0], wh2[1]);
                mma16816(d[mi][3], alo, wh2[2], wh2[3]);
            }

            if (i < 7) {
                // W fragments for the next granule set
                const unsigned wko = (unsigned)((i + 1) * 8 + kq) * 256u;
                LDSM4T(wh1, whiBase + wko);
                LDSM4T(wh2, whiBase + 32768u + wko);
                LDSM4T(wl1, wloBase + wko);
                LDSM4T(wl2, wloBase + 32768u + wko);
                #pragma unroll
                for (int j = 0; j < 4; j++) cur[j] = nxt[j];
            }
        }

        // ---- store m32xn32 fp32 partial (XOR-16 swizzle on rows) @128KB ----
        {
            const unsigned pb = 131072u + (unsigned)((wm * 8 + kq) * 4096);
            #pragma unroll
            for (int mi = 0; mi < 2; mi++) {
                #pragma unroll
                for (int half = 0; half < 2; half++) {
                    const int r = mi * 16 + eg + half * 8;
                    const unsigned xr = (unsigned)((r & 7) * 16);
                    #pragma unroll
                    for (int nt = 0; nt < 4; nt++) {
                        float2 pv;
                        pv.x = d[mi][nt][half * 2 + 0];
                        pv.y = d[mi][nt][half * 2 + 1];
                        unsigned cb = (unsigned)(nt * 32 + ei * 8) ^ xr;
                        *(float2*)(smx + pb + (unsigned)r * 128u + cb) = pv;
                    }
                }
            }
        }
        __syncthreads();                  // sync1: partials visible

        // ---- reduce 8 partials + fused epilogue ----
        float4 o0;
        {
            const unsigned xr = (unsigned)((rl & 7) * 16);
            const unsigned c0 = ((unsigned)(n0 * 4)) ^ xr;
            float4 s0 = {0.f, 0.f, 0.f, 0.f};
            #pragma unroll
            for (int p = 0; p < 8; p++) {
                const char* pp = smx + 131072u + (unsigned)((wmE * 8 + p) * 4096)
                               + (unsigned)rl * 128u;
                float4 a = *(const float4*)(pp + c0);
                s0.x += a.x; s0.y += a.y; s0.z += a.z; s0.w += a.w;
            }

            o0.x = fmaxf(x0p.x + s0.x, 0.f);
            o0.y = fmaxf(x0p.y + s0.y, 0.f);
            o0.z = fmaxf(x0p.z + s0.z, 0.f);
            o0.w = fmaxf(x0p.w + s0.w, 0.f);

            if (t < TT - 1) {
                // write next-step permuted fragments (the cross-CTA dep)
                float sv[4] = {o0.x, o0.y, o0.z, o0.w};
                unsigned* dh = (unsigned*)&g_Ap[t & 1][(tileE * 128 + gE) * 32];
                unsigned* dl = (unsigned*)&g_Ap[t & 1][(tileE * 128 + 64 + gE) * 32];
                #pragma unroll
                for (int j = 0; j < 2; j++) {
                    float v0 = sv[2 * j], v1 = sv[2 * j + 1];
                    __nv_bfloat16 h0 = __float2bfloat16(v0);
                    __nv_bfloat16 h1 = __float2bfloat16(v1);
                    unsigned hw = (unsigned)__bfloat16_as_ushort(h0)
                                | ((unsigned)__bfloat16_as_ushort(h1) << 16);
                    __nv_bfloat16 l0 = __float2bfloat16(v0 - __bfloat162float(h0));
                    __nv_bfloat16 l1 = __float2bfloat16(v1 - __bfloat162float(h1));
                    unsigned lw = (unsigned)__bfloat16_as_ushort(l0)
                                | ((unsigned)__bfloat16_as_ushort(l1) << 16);
                    dh[(L0 + j) * 4 + slot] = hw;
                    dl[(L0 + j) * 4 + slot] = lw;
                }
            }
        }

        __syncthreads();                  // sync2: all frag STGs issued + reads done
        if (t < TT - 1 && tid == 0) {
            __threadfence();
            atomicAdd(barp, 1u);          // arrive; other warps already moving on
        }

        *(float4*)po = o0;                // out-store off the critical path
    }
}

// ---------------------------------------------------------------------------
extern "C" void kernel_launch(void* const* d_in, const int* in_sizes, int n_in,
                              void* d_out, int out_size)
{
    const float* x   = (const float*)d_in[0];
    const float* Wxh = (const float*)d_in[1];
    const float* bxh = (const float*)d_in[2];
    const float* Whh = (const float*)d_in[3];
    float* out = (float*)d_out;

    wx_convert<<<(EE * HH) / 256, 256>>>(Wxh);
    wt_convert<<<(HH * HH) / 256, 256>>>(Whh);

    const int smem_p1 = 2 * 32768;
    cudaFuncSetAttribute(gemm_xh_mma,
                         cudaFuncAttributeMaxDynamicSharedMemorySize, smem_p1);
    dim3 g1(HH / 128, (BB * TT) / 128);
    gemm_xh_mma<<<g1, 256, smem_p1>>>(x, bxh, out);

    init_h0<<<(BB * HH / 2) / 256, 256>>>(out);

    const int smem_p2 = 131072 + 65536;
    cudaFuncSetAttribute(rnn_scan_mma,
                         cudaFuncAttributeMaxDynamicSharedMemorySize, smem_p2);
    rnn_scan_mma<<<NCTA, 512, smem_p2>>>(out);

    bar_reset<<<1, 128>>>();
}

// round 14
// speedup vs baseline: 1.8511x; 1.0172x over previous
#include <cuda_runtime.h>
#include <cuda_bf16.h>

// Problem dims (fixed by the reference)
#define BB   256
#define TT   512
#define EE   512
#define HH   1024
#define LDR  ((long)TT * HH)

#define NCTA 128      // 4 M-tiles (64 rows) x 32 N-tiles (32 cols)

// ---------------------------------------------------------------------------
// Scratch (device globals; no allocation allowed)
// g_Ap[buf][(tile*128 + g)*32 + lane] : hidden state in PRE-PERMUTED mma
//   fragment layout (see round 9 comment).
// ---------------------------------------------------------------------------
__device__ uint4 g_Ap[2][16 * 128 * 32];
__device__ __nv_bfloat16 g_Wkn[2048][HH];
__device__ __nv_bfloat16 g_Wx[1024][HH];

// ---------------------------------------------------------------------------
// PTX helpers
// ---------------------------------------------------------------------------
__device__ __forceinline__ unsigned smem_u32(const void* p) {
    unsigned a;
    asm("{ .reg .u64 t; cvta.to.shared.u64 t, %1; cvt.u32.u64 %0, t; }"
        : "=r"(a) : "l"(p));
    return a;
}

__device__ __forceinline__ unsigned acq_ldu(const unsigned* p) {
    unsigned v;
    asm volatile("ld.acquire.gpu.global.b32 %0, [%1];" : "=r"(v) : "l"(p));
    return v;
}

#define LDSM4(r, a) \
    asm volatile("ldmatrix.sync.aligned.m8n8.x4.shared.b16 {%0,%1,%2,%3}, [%4];" \
        : "=r"((r)[0]), "=r"((r)[1]), "=r"((r)[2]), "=r"((r)[3]) : "r"(a))

#define LDSM4T(r, a) \
    asm volatile("ldmatrix.sync.aligned.m8n8.x4.trans.shared.b16 {%0,%1,%2,%3}, [%4];" \
        : "=r"((r)[0]), "=r"((r)[1]), "=r"((r)[2]), "=r"((r)[3]) : "r"(a))

__device__ __forceinline__ void mma16816(float* d, const unsigned* a,
                                         unsigned b0, unsigned b1) {
    asm volatile(
        "mma.sync.aligned.m16n8k16.row.col.f32.bf16.bf16.f32 "
        "{%0,%1,%2,%3}, {%4,%5,%6,%7}, {%8,%9}, {%0,%1,%2,%3};"
        : "+f"(d[0]), "+f"(d[1]), "+f"(d[2]), "+f"(d[3])
        : "r"(a[0]), "r"(a[1]), "r"(a[2]), "r"(a[3]), "r"(b0), "r"(b1));
}

// pack 8 fp32 -> uint4 hi bf16, uint4 lo bf16
__device__ __forceinline__ void split8(float4 a, float4 b, uint4& hi, uint4& lo) {
    float s[8] = {a.x, a.y, a.z, a.w, b.x, b.y, b.z, b.w};
    unsigned h[4], l[4];
    #pragma unroll
    for (int i = 0; i < 4; i++) {
        __nv_bfloat16 h0 = __float2bfloat16(s[2 * i]);
        __nv_bfloat16 h1 = __float2bfloat16(s[2 * i + 1]);
        __nv_bfloat16 l0 = __float2bfloat16(s[2 * i] - __bfloat162float(h0));
        __nv_bfloat16 l1 = __float2bfloat16(s[2 * i + 1] - __bfloat162float(h1));
        h[i] = (unsigned)__bfloat16_as_ushort(h0)
             | ((unsigned)__bfloat16_as_ushort(h1) << 16);
        l[i] = (unsigned)__bfloat16_as_ushort(l0)
             | ((unsigned)__bfloat16_as_ushort(l1) << 16);
    }
    hi = make_uint4(h[0], h[1], h[2], h[3]);
    lo = make_uint4(l[0], l[1], l[2], l[3]);
}

// ---------------------------------------------------------------------------
// Per-bm-group barrier counters (4 independent groups of 32 CTAs)
// ---------------------------------------------------------------------------
__device__ unsigned int g_bar4[4 * 32];
__global__ void bar_reset() {
    if (threadIdx.x < 128) g_bar4[threadIdx.x] = 0;
}

// ---------------------------------------------------------------------------
// Prep kernels
// ---------------------------------------------------------------------------
__global__ void __launch_bounds__(256)
wt_convert(const float* __restrict__ Whh)
{
    int idx = blockIdx.x * 256 + threadIdx.x;
    int k = idx >> 10, n = idx & 1023;
    float w = Whh[(long)k * HH + n];
    __nv_bfloat16 hi = __float2bfloat16(w);
    __nv_bfloat16 lo = __float2bfloat16(w - __bfloat162float(hi));
    g_Wkn[k][n] = hi;
    g_Wkn[1024 + k][n] = lo;
}

__global__ void __launch_bounds__(256)
wx_convert(const float* __restrict__ Wxh)
{
    int idx = blockIdx.x * 256 + threadIdx.x;
    int k = idx >> 10, n = idx & 1023;
    float w = Wxh[(long)k * HH + n];
    __nv_bfloat16 hi = __float2bfloat16(w);
    __nv_bfloat16 lo = __float2bfloat16(w - __bfloat162float(hi));
    g_Wx[k][n] = hi;
    g_Wx[512 + k][n] = lo;
}

__global__ void __launch_bounds__(256)
init_h0(float* __restrict__ out)
{
    int idx = blockIdx.x * 256 + threadIdx.x;   // 0 .. 128K-1
    int b  = idx >> 9;
    int c2 = (idx & 511) * 2;
    float* p = out + (long)b * LDR + c2;
    float v0 = fmaxf(p[0], 0.f);
    float v1 = fmaxf(p[1], 0.f);
    p[0] = v0; p[1] = v1;

    __nv_bfloat16 h0 = __float2bfloat16(v0);
    __nv_bfloat16 h1 = __float2bfloat16(v1);
    unsigned hw = (unsigned)__bfloat16_as_ushort(h0)
                | ((unsigned)__bfloat16_as_ushort(h1) << 16);
    __nv_bfloat16 l0 = __float2bfloat16(v0 - __bfloat162float(h0));
    __nv_bfloat16 l1 = __float2bfloat16(v1 - __bfloat162float(h1));
    unsigned lw = (unsigned)__bfloat16_as_ushort(l0)
                | ((unsigned)__bfloat16_as_ushort(l1) << 16);

    int tile = b >> 4;
    int rloc = b & 15;
    int g    = c2 >> 4;
    int cb   = c2 & 15;
    int L    = ((rloc & 7) << 2) + ((cb & 7) >> 1);
    int slot = ((rloc & 8) ? 1 : 0) | ((cb & 8) ? 2 : 0);

    unsigned* dh = (unsigned*)&g_Ap[0][(tile * 128 + g) * 32 + L];
    unsigned* dl = (unsigned*)&g_Ap[0][(tile * 128 + 64 + g) * 32 + L];
    dh[slot] = hw;
    dl[slot] = lw;
}

// ---------------------------------------------------------------------------
// Phase 1 (tensor): xh = x @ Wxh + bxh  (unchanged)
// ---------------------------------------------------------------------------
extern __shared__ char smx[];

#define AFX(kg, m) ((unsigned)((kg) * 2048 + ((m) >> 3) * 128 + ((((m) & 7) ^ (kg)) * 16)))

__global__ void __launch_bounds__(256)
gemm_xh_mma(const float* __restrict__ x,
            const float* __restrict__ bias,
            float* __restrict__ C)
{
    const int tid  = threadIdx.x;
    const int wid  = tid >> 5;
    const int lane = tid & 31;
    const int wr   = wid & 3;
    const int wc   = wid >> 2;
    const int bm   = blockIdx.y;
    const int bn   = blockIdx.x;

    const unsigned sb = smem_u32(smx);
    const int q   = lane >> 3;
    const int l7  = lane & 7;
    const int kgq = q >> 1;

    const int am = tid & 127;
    const int wk = tid & 31;

    float2 breg[8];
    #pragma unroll
    for (int n8 = 0; n8 < 8; n8++)
        breg[n8] = *(const float2*)&bias[bn * 128 + wc * 64 + n8 * 8 + (lane & 3) * 2];

    float acc[2][8][4];
    #pragma unroll
    for (int m = 0; m < 2; m++)
        #pragma unroll
        for (int n = 0; n < 8; n++)
            #pragma unroll
            for (int j = 0; j < 4; j++) acc[m][n][j] = 0.f;

    const float* xb = x + (long)(bm * 128) * EE;

    float4 xa[2][2];
    uint4  wvh[2], wvl[2];
    #pragma unroll
    for (int i = 0; i < 2; i++) {
        int idx = tid + i * 256;
        int kg = idx >> 7;
        const float* p = xb + (long)am * EE + kg * 8;
        xa[i][0] = *(const float4*)p;
        xa[i][1] = *(const float4*)(p + 4);
        int pp = (idx >> 5) & 15;
        wvh[i] = *(const uint4*)&g_Wx[wk][bn * 128 + pp * 8];
        wvl[i] = *(const uint4*)&g_Wx[512 + wk][bn * 128 + pp * 8];
    }
    #pragma unroll
    for (int i = 0; i < 2; i++) {
        int idx = tid + i * 256;
        int kg = idx >> 7;
        uint4 hi, lo;
        split8(xa[i][0], xa[i][1], hi, lo);
        unsigned ao = AFX(kg, am);
        *(uint4*)(smx + ao)         = hi;
        *(uint4*)(smx + 8192 + ao)  = lo;
        int pp = (idx >> 5) & 15;
        unsigned wo = 16384u + (unsigned)pp * 512u + (unsigned)wk * 16u;
        *(uint4*)(smx + wo)         = wvh[i];
        *(uint4*)(smx + 8192 + wo)  = wvl[i];
    }
    __syncthreads();

    unsigned buf = 0;
    for (int kc = 0; kc < 16; kc++) {
        const bool more = (kc + 1 < 16);
        if (more) {
            const int k0 = (kc + 1) * 32;
            #pragma unroll
            for (int i = 0; i < 2; i++) {
                int idx = tid + i * 256;
                int kg = idx >> 7;
                const float* p = xb + (long)am * EE + k0 + kg * 8;
                xa[i][0] = *(const float4*)p;
                xa[i][1] = *(const float4*)(p + 4);
                int pp = (idx >> 5) & 15;
                wvh[i] = *(const uint4*)&g_Wx[k0 + wk][bn * 128 + pp * 8];
                wvl[i] = *(const uint4*)&g_Wx[512 + k0 + wk][bn * 128 + pp * 8];
            }
        }

        const unsigned B0 = sb + buf * 32768u;
        #pragma unroll
        for (int s16 = 0; s16 < 2; s16++) {
            const int kg = s16 * 2 + kgq;
            const unsigned aoff = (unsigned)kg * 2048u + (unsigned)((l7 ^ kg) * 16);
            unsigned ahi[2][4], alo[2][4];
            LDSM4(ahi[0], B0 + aoff + (unsigned)(wr * 4 + 0 + (q & 1)) * 128u);
            LDSM4(ahi[1], B0 + aoff + (unsigned)(wr * 4 + 2 + (q & 1)) * 128u);
            LDSM4(alo[0], B0 + 8192u + aoff + (unsigned)(wr * 4 + 0 + (q & 1)) * 128u);
            LDSM4(alo[1], B0 + 8192u + aoff + (unsigned)(wr * 4 + 2 + (q & 1)) * 128u);

            const unsigned wrow = (unsigned)(s16 * 16 + (q & 1) * 8 + l7) * 16u;
            #pragma unroll
            for (int pp = 0; pp < 4; pp++) {
                unsigned wh[4], wl[4];
                unsigned wbase = B0 + 16384u
                               + (unsigned)(wc * 8 + pp * 2 + kgq) * 512u + wrow;
                LDSM4T(wh, wbase);
                LDSM4T(wl, wbase + 8192u);
                const int n0 = pp * 2, n1 = pp * 2 + 1;
                mma16816(acc[0][n0], ahi[0], wh[0], wh[1]);
                mma16816(acc[0][n1], ahi[0], wh[2], wh[3]);
                mma16816(acc[1][n0], ahi[1], wh[0], wh[1]);
                mma16816(acc[1][n1], ahi[1], wh[2], wh[3]);
                mma16816(acc[0][n0], alo[0], wh[0], wh[1]);
                mma16816(acc[0][n1], alo[0], wh[2], wh[3]);
                mma16816(acc[1][n0], alo[1], wh[0], wh[1]);
                mma16816(acc[1][n1], alo[1], wh[2], wh[3]);
                mma16816(acc[0][n0], ahi[0], wl[0], wl[1]);
                mma16816(acc[0][n1], ahi[0], wl[2], wl[3]);
                mma16816(acc[1][n0], ahi[1], wl[0], wl[1]);
                mma16816(acc[1][n1], ahi[1], wl[2], wl[3]);
            }
        }

        if (more) {
            const unsigned nb = (buf ^ 1u) * 32768u;
            #pragma unroll
            for (int i = 0; i < 2; i++) {
                int idx = tid + i * 256;
                int kg = idx >> 7;
                uint4 hi, lo;
                split8(xa[i][0], xa[i][1], hi, lo);
                unsigned ao = nb + AFX(kg, am);
                *(uint4*)(smx + ao)        = hi;
                *(uint4*)(smx + 8192 + ao) = lo;
                int pp = (idx >> 5) & 15;
                unsigned wo = nb + 16384u + (unsigned)pp * 512u + (unsigned)wk * 16u;
                *(uint4*)(smx + wo)        = wvh[i];
                *(uint4*)(smx + 8192 + wo) = wvl[i];
            }
            __syncthreads();
            buf ^= 1u;
        }
    }

    #pragma unroll
    for (int mm = 0; mm < 2; mm++) {
        #pragma unroll
        for (int half = 0; half < 2; half++) {
            long row = (long)bm * 128 + wr * 32 + mm * 16 + (lane >> 2) + half * 8;
            float* pr = C + row * HH + bn * 128 + wc * 64 + (lane & 3) * 2;
            #pragma unroll
            for (int n8 = 0; n8 < 8; n8++) {
                float2 o;
                o.x = acc[mm][n8][half * 2 + 0] + breg[n8].x;
                o.y = acc[mm][n8][half * 2 + 1] + breg[n8].y;
                *(float2*)(pr + n8 * 8) = o;
            }
        }
    }
}

// ---------------------------------------------------------------------------
// Phase 2: persistent mma.sync scan — round-13 structure, MMAs reordered by
// product group across both mi so each accumulator's reuse distance is 8
// instructions (was 4), covering HMMA latency.
// ---------------------------------------------------------------------------
__global__ void __launch_bounds__(512, 1)
rnn_scan_mma(float* __restrict__ out)
{
    const int tid  = threadIdx.x;
    const int wid  = tid >> 5;
    const int kq   = wid & 7;
    const int wm   = wid >> 3;
    const int lane = tid & 31;
    const int bm   = blockIdx.x >> 5;
    const int bn   = blockIdx.x & 31;

    const unsigned sb = smem_u32(smx);

    // ---- stage W slice into SMEM panels (once): hi @0, lo @65536 ----
    for (int i = 0; i < 16; i++) {
        int kk = i * 128 + (tid >> 2);
        int p  = tid & 3;
        uint4 v = *(const uint4*)&g_Wkn[kk][bn * 32 + p * 8];
        unsigned off = (unsigned)(kk >> 10) * 65536u
                     + (unsigned)p * 16384u + (unsigned)(kk & 1023) * 16u;
        *(uint4*)(smx + off) = v;
    }
    __syncthreads();

    // W ldmatrix lane addressing
    const int q   = lane >> 3;
    const int l7  = lane & 7;
    const int kgq = q >> 1;
    const unsigned wrowsel = (unsigned)((q & 1) * 8 + l7) * 16u;
    const unsigned whiBase = sb + (unsigned)kgq * 16384u + wrowsel;
    const unsigned wloBase = whiBase + 65536u;

    // partial-store mapping
    const int eg = lane >> 2;
    const int ei = lane & 3;
    // reduction / epilogue mapping
    const int r64 = tid >> 3;
    const int n0  = (tid & 7) * 4;

    const int bm4 = bm * 4;
    unsigned* const barp = &g_bar4[bm * 32];

    // epilogue constants
    const int gb    = bm * 64 + r64;
    const int tileE = gb >> 4;
    const int rloc  = gb & 15;
    const int Cb    = bn * 32 + n0;
    const int gE    = Cb >> 4;
    const int slot  = ((rloc & 8) ? 1 : 0) | ((Cb & 8) ? 2 : 0);
    const int L0    = ((rloc & 7) << 2) + ((n0 & 7) >> 1);
    const int wmE = r64 >> 5;
    const int rl  = r64 & 31;

    for (int t = 1; t < TT; t++) {
        const uint4* Ab = &g_Ap[(t + 1) & 1][0];

        // ---- pre-wait prologue (independent of producers) ----
        float* po = out + (long)gb * LDR + (long)t * HH + Cb;
        float4 x0p = *(const float4*)po;

        unsigned wh1[4], wh2[4], wl1[4], wl2[4];
        {
            const unsigned wko0 = (unsigned)kq * 256u;
            LDSM4T(wh1, whiBase + wko0);
            LDSM4T(wh2, whiBase + 32768u + wko0);
            LDSM4T(wl1, wloBase + wko0);
            LDSM4T(wl2, wloBase + 32768u + wko0);
        }

        float d[2][4][4];
        #pragma unroll
        for (int mi = 0; mi < 2; mi++)
            #pragma unroll
            for (int nt = 0; nt < 4; nt++)
                #pragma unroll
                for (int j = 0; j < 4; j++) d[mi][nt][j] = 0.f;

        // ---- warp-autonomous wait: producers published step t-1 ----
        if (t > 1) {
            const unsigned tgt = (unsigned)(t - 1) * 32u;
            while (acq_ldu(barp) < tgt) __nanosleep(32);
        }

        uint4 cur[4], nxt[4];
        #pragma unroll
        for (int mi = 0; mi < 2; mi++) {
            const int tl = bm4 + wm * 2 + mi;
            cur[mi * 2 + 0] = Ab[(tl * 128 + kq) * 32 + lane];
            cur[mi * 2 + 1] = Ab[(tl * 128 + 64 + kq) * 32 + lane];
        }

        #pragma unroll
        for (int i = 0; i < 8; i++) {
            if (i < 7) {
                const int gk1 = (i + 1) * 8 + kq;
                #pragma unroll
                for (int mi = 0; mi < 2; mi++) {
                    const int tl = bm4 + wm * 2 + mi;
                    nxt[mi * 2 + 0] = Ab[(tl * 128 + gk1) * 32 + lane];
                    nxt[mi * 2 + 1] = Ab[(tl * 128 + 64 + gk1) * 32 + lane];
                }
            }

            const unsigned* ahi0 = (const unsigned*)&cur[0];
            const unsigned* alo0 = (const unsigned*)&cur[1];
            const unsigned* ahi1 = (const unsigned*)&cur[2];
            const unsigned* alo1 = (const unsigned*)&cur[3];

            // product group 1: Ahi x Whi  (reuse distance 8)
            mma16816(d[0][0], ahi0, wh1[0], wh1[1]);
            mma16816(d[0][1], ahi0, wh1[2], wh1[3]);
            mma16816(d[0][2], ahi0, wh2[0], wh2[1]);
            mma16816(d[0][3], ahi0, wh2[2], wh2[3]);
            mma16816(d[1][0], ahi1, wh1[0], wh1[1]);
            mma16816(d[1][1], ahi1, wh1[2], wh1[3]);
            mma16816(d[1][2], ahi1, wh2[0], wh2[1]);
            mma16816(d[1][3], ahi1, wh2[2], wh2[3]);
            // product group 2: Ahi x Wlo
            mma16816(d[0][0], ahi0, wl1[0], wl1[1]);
            mma16816(d[0][1], ahi0, wl1[2], wl1[3]);
            mma16816(d[0][2], ahi0, wl2[0], wl2[1]);
            mma16816(d[0][3], ahi0, wl2[2], wl2[3]);
            mma16816(d[1][0], ahi1, wl1[0], wl1[1]);
            mma16816(d[1][1], ahi1, wl1[2], wl1[3]);
            mma16816(d[1][2], ahi1, wl2[0], wl2[1]);
            mma16816(d[1][3], ahi1, wl2[2], wl2[3]);
            // product group 3: Alo x Whi
            mma16816(d[0][0], alo0, wh1[0], wh1[1]);
            mma16816(d[0][1], alo0, wh1[2], wh1[3]);
            mma16816(d[0][2], alo0, wh2[0], wh2[1]);
            mma16816(d[0][3], alo0, wh2[2], wh2[3]);
            mma16816(d[1][0], alo1, wh1[0], wh1[1]);
            mma16816(d[1][1], alo1, wh1[2], wh1[3]);
            mma16816(d[1][2], alo1, wh2[0], wh2[1]);
            mma16816(d[1][3], alo1, wh2[2], wh2[3]);

            if (i < 7) {
                const unsigned wko = (unsigned)((i + 1) * 8 + kq) * 256u;
                LDSM4T(wh1, whiBase + wko);
                LDSM4T(wh2, whiBase + 32768u + wko);
                LDSM4T(wl1, wloBase + wko);
                LDSM4T(wl2, wloBase + 32768u + wko);
                #pragma unroll
                for (int j = 0; j < 4; j++) cur[j] = nxt[j];
            }
        }

        // ---- store m32xn32 fp32 partial (XOR-16 swizzle on rows) @128KB ----
        {
            const unsigned pb = 131072u + (unsigned)((wm * 8 + kq) * 4096);
            #pragma unroll
            for (int mi = 0; mi < 2; mi++) {
                #pragma unroll
                for (int half = 0; half < 2; half++) {
                    const int r = mi * 16 + eg + half * 8;
                    const unsigned xr = (unsigned)((r & 7) * 16);
                    #pragma unroll
                    for (int nt = 0; nt < 4; nt++) {
                        float2 pv;
                        pv.x = d[mi][nt][half * 2 + 0];
                        pv.y = d[mi][nt][half * 2 + 1];
                        unsigned cb = (unsigned)(nt * 32 + ei * 8) ^ xr;
                        *(float2*)(smx + pb + (unsigned)r * 128u + cb) = pv;
                    }
                }
            }
        }
        __syncthreads();                  // sync1: partials visible

        // ---- reduce 8 partials + fused epilogue ----
        float4 o0;
        {
            const unsigned xr = (unsigned)((rl & 7) * 16);
            const unsigned c0 = ((unsigned)(n0 * 4)) ^ xr;
            float4 s0 = {0.f, 0.f, 0.f, 0.f};
            #pragma unroll
            for (int p = 0; p < 8; p++) {
                const char* pp = smx + 131072u + (unsigned)((wmE * 8 + p) * 4096)
                               + (unsigned)rl * 128u;
                float4 a = *(const float4*)(pp + c0);
                s0.x += a.x; s0.y += a.y; s0.z += a.z; s0.w += a.w;
            }

            o0.x = fmaxf(x0p.x + s0.x, 0.f);
            o0.y = fmaxf(x0p.y + s0.y, 0.f);
            o0.z = fmaxf(x0p.z + s0.z, 0.f);
            o0.w = fmaxf(x0p.w + s0.w, 0.f);

            if (t < TT - 1) {
                // write next-step permuted fragments (the cross-CTA dep)
                float sv[4] = {o0.x, o0.y, o0.z, o0.w};
                unsigned* dh = (unsigned*)&g_Ap[t & 1][(tileE * 128 + gE) * 32];
                unsigned* dl = (unsigned*)&g_Ap[t & 1][(tileE * 128 + 64 + gE) * 32];
                #pragma unroll
                for (int j = 0; j < 2; j++) {
                    float v0 = sv[2 * j], v1 = sv[2 * j + 1];
                    __nv_bfloat16 h0 = __float2bfloat16(v0);
                    __nv_bfloat16 h1 = __float2bfloat16(v1);
                    unsigned hw = (unsigned)__bfloat16_as_ushort(h0)
                                | ((unsigned)__bfloat16_as_ushort(h1) << 16);
                    __nv_bfloat16 l0 = __float2bfloat16(v0 - __bfloat162float(h0));
                    __nv_bfloat16 l1 = __float2bfloat16(v1 - __bfloat162float(h1));
                    unsigned lw = (unsigned)__bfloat16_as_ushort(l0)
                                | ((unsigned)__bfloat16_as_ushort(l1) << 16);
                    dh[(L0 + j) * 4 + slot] = hw;
                    dl[(L0 + j) * 4 + slot] = lw;
                }
            }
        }

        __syncthreads();                  // sync2: frag STGs issued + reads done
        if (t < TT - 1 && tid == 0) {
            __threadfence();
            atomicAdd(barp, 1u);
        }

        *(float4*)po = o0;                // out-store off the critical path
    }
}

// ---------------------------------------------------------------------------
extern "C" void kernel_launch(void* const* d_in, const int* in_sizes, int n_in,
                              void* d_out, int out_size)
{
    const float* x   = (const float*)d_in[0];
    const float* Wxh = (const float*)d_in[1];
    const float* bxh = (const float*)d_in[2];
    const float* Whh = (const float*)d_in[3];
    float* out = (float*)d_out;

    wx_convert<<<(EE * HH) / 256, 256>>>(Wxh);
    wt_convert<<<(HH * HH) / 256, 256>>>(Whh);

    const int smem_p1 = 2 * 32768;
    cudaFuncSetAttribute(gemm_xh_mma,
                         cudaFuncAttributeMaxDynamicSharedMemorySize, smem_p1);
    dim3 g1(HH / 128, (BB * TT) / 128);
    gemm_xh_mma<<<g1, 256, smem_p1>>>(x, bxh, out);

    init_h0<<<(BB * HH / 2) / 256, 256>>>(out);

    const int smem_p2 = 131072 + 65536;
    cudaFuncSetAttribute(rnn_scan_mma,
                         cudaFuncAttributeMaxDynamicSharedMemorySize, smem_p2);
    rnn_scan_mma<<<NCTA, 512, smem_p2>>>(out);

    bar_reset<<<1, 128>>>();
}

// round 15
// speedup vs baseline: 2.2498x; 1.2154x over previous
#include <cuda_runtime.h>
#include <cuda_bf16.h>
#include <cuda_fp16.h>

// Problem dims (fixed by the reference)
#define BB   256
#define TT   512
#define EE   512
#define HH   1024
#define LDR  ((long)TT * HH)

#define NCTA 128      // 4 M-tiles (64 rows) x 32 N-tiles (32 cols)

// ---------------------------------------------------------------------------
// Scratch (device globals; no allocation allowed)
// g_Ap[buf][(tile*64 + g)*32 + lane] : hidden state as fp16 PRE-PERMUTED mma
//   fragments. tile = row>>4 (16 tiles), g = k16 granule 0..63. Lane L uint4:
//     a0 = A[L>>2][(L&3)*2+0/1], a1 = A[8+(L>>2)][...], a2/a3 = +8 cols.
// g_Wkn[kk][n]: Whh fp16 [k][n]: kk<1024 = hi, kk>=1024 = lo (residual).
// ---------------------------------------------------------------------------
__device__ uint4 g_Ap[2][16 * 64 * 32];
__device__ __half g_Wkn[2048][HH];
__device__ __nv_bfloat16 g_Wx[1024][HH];   // phase-1 weights (bf16 hi/lo)

// ---------------------------------------------------------------------------
// PTX helpers
// ---------------------------------------------------------------------------
__device__ __forceinline__ unsigned smem_u32(const void* p) {
    unsigned a;
    asm("{ .reg .u64 t; cvta.to.shared.u64 t, %1; cvt.u32.u64 %0, t; }"
        : "=r"(a) : "l"(p));
    return a;
}

__device__ __forceinline__ unsigned acq_ldu(const unsigned* p) {
    unsigned v;
    asm volatile("ld.acquire.gpu.global.b32 %0, [%1];" : "=r"(v) : "l"(p));
    return v;
}

#define LDSM4(r, a) \
    asm volatile("ldmatrix.sync.aligned.m8n8.x4.shared.b16 {%0,%1,%2,%3}, [%4];" \
        : "=r"((r)[0]), "=r"((r)[1]), "=r"((r)[2]), "=r"((r)[3]) : "r"(a))

#define LDSM4T(r, a) \
    asm volatile("ldmatrix.sync.aligned.m8n8.x4.trans.shared.b16 {%0,%1,%2,%3}, [%4];" \
        : "=r"((r)[0]), "=r"((r)[1]), "=r"((r)[2]), "=r"((r)[3]) : "r"(a))

// bf16 mma (phase 1)
__device__ __forceinline__ void mma16816(float* d, const unsigned* a,
                                         unsigned b0, unsigned b1) {
    asm volatile(
        "mma.sync.aligned.m16n8k16.row.col.f32.bf16.bf16.f32 "
        "{%0,%1,%2,%3}, {%4,%5,%6,%7}, {%8,%9}, {%0,%1,%2,%3};"
        : "+f"(d[0]), "+f"(d[1]), "+f"(d[2]), "+f"(d[3])
        : "r"(a[0]), "r"(a[1]), "r"(a[2]), "r"(a[3]), "r"(b0), "r"(b1));
}

// fp16 mma (scan)
__device__ __forceinline__ void mma16816h(float* d, const unsigned* a,
                                          unsigned b0, unsigned b1) {
    asm volatile(
        "mma.sync.aligned.m16n8k16.row.col.f32.f16.f16.f32 "
        "{%0,%1,%2,%3}, {%4,%5,%6,%7}, {%8,%9}, {%0,%1,%2,%3};"
        : "+f"(d[0]), "+f"(d[1]), "+f"(d[2]), "+f"(d[3])
        : "r"(a[0]), "r"(a[1]), "r"(a[2]), "r"(a[3]), "r"(b0), "r"(b1));
}

// pack 8 fp32 -> uint4 hi bf16, uint4 lo bf16 (phase-1 staging)
__device__ __forceinline__ void split8(float4 a, float4 b, uint4& hi, uint4& lo) {
    float s[8] = {a.x, a.y, a.z, a.w, b.x, b.y, b.z, b.w};
    unsigned h[4], l[4];
    #pragma unroll
    for (int i = 0; i < 4; i++) {
        __nv_bfloat16 h0 = __float2bfloat16(s[2 * i]);
        __nv_bfloat16 h1 = __float2bfloat16(s[2 * i + 1]);
        __nv_bfloat16 l0 = __float2bfloat16(s[2 * i] - __bfloat162float(h0));
        __nv_bfloat16 l1 = __float2bfloat16(s[2 * i + 1] - __bfloat162float(h1));
        h[i] = (unsigned)__bfloat16_as_ushort(h0)
             | ((unsigned)__bfloat16_as_ushort(h1) << 16);
        l[i] = (unsigned)__bfloat16_as_ushort(l0)
             | ((unsigned)__bfloat16_as_ushort(l1) << 16);
    }
    hi = make_uint4(h[0], h[1], h[2], h[3]);
    lo = make_uint4(l[0], l[1], l[2], l[3]);
}

__device__ __forceinline__ unsigned pack_h2(float v0, float v1) {
    __half2 h = __floats2half2_rn(v0, v1);
    return *(unsigned*)&h;
}

// ---------------------------------------------------------------------------
// Per-bm-group barrier counters (4 independent groups of 32 CTAs)
// ---------------------------------------------------------------------------
__device__ unsigned int g_bar4[4 * 32];
__global__ void bar_reset() {
    if (threadIdx.x < 128) g_bar4[threadIdx.x] = 0;
}

// ---------------------------------------------------------------------------
// Prep kernels
// ---------------------------------------------------------------------------
__global__ void __launch_bounds__(256)
wt_convert(const float* __restrict__ Whh)
{
    int idx = blockIdx.x * 256 + threadIdx.x;
    int k = idx >> 10, n = idx & 1023;
    float w = Whh[(long)k * HH + n];
    __half hi = __float2half_rn(w);
    __half lo = __float2half_rn(w - __half2float(hi));
    g_Wkn[k][n] = hi;
    g_Wkn[1024 + k][n] = lo;
}

__global__ void __launch_bounds__(256)
wx_convert(const float* __restrict__ Wxh)
{
    int idx = blockIdx.x * 256 + threadIdx.x;
    int k = idx >> 10, n = idx & 1023;
    float w = Wxh[(long)k * HH + n];
    __nv_bfloat16 hi = __float2bfloat16(w);
    __nv_bfloat16 lo = __float2bfloat16(w - __bfloat162float(hi));
    g_Wx[k][n] = hi;
    g_Wx[512 + k][n] = lo;
}

// h_0 = relu(xh_0) in place + permuted fp16 fragments into g_Ap[0]
__global__ void __launch_bounds__(256)
init_h0(float* __restrict__ out)
{
    int idx = blockIdx.x * 256 + threadIdx.x;   // 0 .. 128K-1
    int b  = idx >> 9;
    int c2 = (idx & 511) * 2;
    float* p = out + (long)b * LDR + c2;
    float v0 = fmaxf(p[0], 0.f);
    float v1 = fmaxf(p[1], 0.f);
    p[0] = v0; p[1] = v1;

    unsigned hw = pack_h2(v0, v1);

    int tile = b >> 4;
    int rloc = b & 15;
    int g    = c2 >> 4;
    int cb   = c2 & 15;
    int L    = ((rloc & 7) << 2) + ((cb & 7) >> 1);
    int slot = ((rloc & 8) ? 1 : 0) | ((cb & 8) ? 2 : 0);

    unsigned* dh = (unsigned*)&g_Ap[0][(tile * 64 + g) * 32 + L];
    dh[slot] = hw;
}

// ---------------------------------------------------------------------------
// Phase 1 (tensor): xh = x @ Wxh + bxh  (bf16 x3, unchanged)
// ---------------------------------------------------------------------------
extern __shared__ char smx[];

#define AFX(kg, m) ((unsigned)((kg) * 2048 + ((m) >> 3) * 128 + ((((m) & 7) ^ (kg)) * 16)))

__global__ void __launch_bounds__(256)
gemm_xh_mma(const float* __restrict__ x,
            const float* __restrict__ bias,
            float* __restrict__ C)
{
    const int tid  = threadIdx.x;
    const int wid  = tid >> 5;
    const int lane = tid & 31;
    const int wr   = wid & 3;
    const int wc   = wid >> 2;
    const int bm   = blockIdx.y;
    const int bn   = blockIdx.x;

    const unsigned sb = smem_u32(smx);
    const int q   = lane >> 3;
    const int l7  = lane & 7;
    const int kgq = q >> 1;

    const int am = tid & 127;
    const int wk = tid & 31;

    float2 breg[8];
    #pragma unroll
    for (int n8 = 0; n8 < 8; n8++)
        breg[n8] = *(const float2*)&bias[bn * 128 + wc * 64 + n8 * 8 + (lane & 3) * 2];

    float acc[2][8][4];
    #pragma unroll
    for (int m = 0; m < 2; m++)
        #pragma unroll
        for (int n = 0; n < 8; n++)
            #pragma unroll
            for (int j = 0; j < 4; j++) acc[m][n][j] = 0.f;

    const float* xb = x + (long)(bm * 128) * EE;

    float4 xa[2][2];
    uint4  wvh[2], wvl[2];
    #pragma unroll
    for (int i = 0; i < 2; i++) {
        int idx = tid + i * 256;
        int kg = idx >> 7;
        const float* p = xb + (long)am * EE + kg * 8;
        xa[i][0] = *(const float4*)p;
        xa[i][1] = *(const float4*)(p + 4);
        int pp = (idx >> 5) & 15;
        wvh[i] = *(const uint4*)&g_Wx[wk][bn * 128 + pp * 8];
        wvl[i] = *(const uint4*)&g_Wx[512 + wk][bn * 128 + pp * 8];
    }
    #pragma unroll
    for (int i = 0; i < 2; i++) {
        int idx = tid + i * 256;
        int kg = idx >> 7;
        uint4 hi, lo;
        split8(xa[i][0], xa[i][1], hi, lo);
        unsigned ao = AFX(kg, am);
        *(uint4*)(smx + ao)         = hi;
        *(uint4*)(smx + 8192 + ao)  = lo;
        int pp = (idx >> 5) & 15;
        unsigned wo = 16384u + (unsigned)pp * 512u + (unsigned)wk * 16u;
        *(uint4*)(smx + wo)         = wvh[i];
        *(uint4*)(smx + 8192 + wo)  = wvl[i];
    }
    __syncthreads();

    unsigned buf = 0;
    for (int kc = 0; kc < 16; kc++) {
        const bool more = (kc + 1 < 16);
        if (more) {
            const int k0 = (kc + 1) * 32;
            #pragma unroll
            for (int i = 0; i < 2; i++) {
                int idx = tid + i * 256;
                int kg = idx >> 7;
                const float* p = xb + (long)am * EE + k0 + kg * 8;
                xa[i][0] = *(const float4*)p;
                xa[i][1] = *(const float4*)(p + 4);
                int pp = (idx >> 5) & 15;
                wvh[i] = *(const uint4*)&g_Wx[k0 + wk][bn * 128 + pp * 8];
                wvl[i] = *(const uint4*)&g_Wx[512 + k0 + wk][bn * 128 + pp * 8];
            }
        }

        const unsigned B0 = sb + buf * 32768u;
        #pragma unroll
        for (int s16 = 0; s16 < 2; s16++) {
            const int kg = s16 * 2 + kgq;
            const unsigned aoff = (unsigned)kg * 2048u + (unsigned)((l7 ^ kg) * 16);
            unsigned ahi[2][4], alo[2][4];
            LDSM4(ahi[0], B0 + aoff + (unsigned)(wr * 4 + 0 + (q & 1)) * 128u);
            LDSM4(ahi[1], B0 + aoff + (unsigned)(wr * 4 + 2 + (q & 1)) * 128u);
            LDSM4(alo[0], B0 + 8192u + aoff + (unsigned)(wr * 4 + 0 + (q & 1)) * 128u);
            LDSM4(alo[1], B0 + 8192u + aoff + (unsigned)(wr * 4 + 2 + (q & 1)) * 128u);

            const unsigned wrow = (unsigned)(s16 * 16 + (q & 1) * 8 + l7) * 16u;
            #pragma unroll
            for (int pp = 0; pp < 4; pp++) {
                unsigned wh[4], wl[4];
                unsigned wbase = B0 + 16384u
                               + (unsigned)(wc * 8 + pp * 2 + kgq) * 512u + wrow;
                LDSM4T(wh, wbase);
                LDSM4T(wl, wbase + 8192u);
                const int n0 = pp * 2, n1 = pp * 2 + 1;
                mma16816(acc[0][n0], ahi[0], wh[0], wh[1]);
                mma16816(acc[0][n1], ahi[0], wh[2], wh[3]);
                mma16816(acc[1][n0], ahi[1], wh[0], wh[1]);
                mma16816(acc[1][n1], ahi[1], wh[2], wh[3]);
                mma16816(acc[0][n0], alo[0], wh[0], wh[1]);
                mma16816(acc[0][n1], alo[0], wh[2], wh[3]);
                mma16816(acc[1][n0], alo[1], wh[0], wh[1]);
                mma16816(acc[1][n1], alo[1], wh[2], wh[3]);
                mma16816(acc[0][n0], ahi[0], wl[0], wl[1]);
                mma16816(acc[0][n1], ahi[0], wl[2], wl[3]);
                mma16816(acc[1][n0], ahi[1], wl[0], wl[1]);
                mma16816(acc[1][n1], ahi[1], wl[2], wl[3]);
            }
        }

        if (more) {
            const unsigned nb = (buf ^ 1u) * 32768u;
            #pragma unroll
            for (int i = 0; i < 2; i++) {
                int idx = tid + i * 256;
                int kg = idx >> 7;
                uint4 hi, lo;
                split8(xa[i][0], xa[i][1], hi, lo);
                unsigned ao = nb + AFX(kg, am);
                *(uint4*)(smx + ao)        = hi;
                *(uint4*)(smx + 8192 + ao) = lo;
                int pp = (idx >> 5) & 15;
                unsigned wo = nb + 16384u + (unsigned)pp * 512u + (unsigned)wk * 16u;
                *(uint4*)(smx + wo)        = wvh[i];
                *(uint4*)(smx + 8192 + wo) = wvl[i];
            }
            __syncthreads();
            buf ^= 1u;
        }
    }

    #pragma unroll
    for (int mm = 0; mm < 2; mm++) {
        #pragma unroll
        for (int half = 0; half < 2; half++) {
            long row = (long)bm * 128 + wr * 32 + mm * 16 + (lane >> 2) + half * 8;
            float* pr = C + row * HH + bn * 128 + wc * 64 + (lane & 3) * 2;
            #pragma unroll
            for (int n8 = 0; n8 < 8; n8++) {
                float2 o;
                o.x = acc[mm][n8][half * 2 + 0] + breg[n8].x;
                o.y = acc[mm][n8][half * 2 + 1] + breg[n8].y;
                *(float2*)(pr + n8 * 8) = o;
            }
        }
    }
}

// ---------------------------------------------------------------------------
// Phase 2: persistent fp16 mma.sync scan — 2 products per granule:
// A(fp16) x Whi + A(fp16) x Wlo (W fp16 hi/lo pair). Fragment-resident A,
// round-13/14 sync (warp-autonomous wait, 2 CTA syncs per step).
// ---------------------------------------------------------------------------
__global__ void __launch_bounds__(512, 1)
rnn_scan_mma(float* __restrict__ out)
{
    const int tid  = threadIdx.x;
    const int wid  = tid >> 5;
    const int kq   = wid & 7;
    const int wm   = wid >> 3;
    const int lane = tid & 31;
    const int bm   = blockIdx.x >> 5;
    const int bn   = blockIdx.x & 31;

    const unsigned sb = smem_u32(smx);

    // ---- stage W slice into SMEM panels (once): hi @0, lo @65536 ----
    for (int i = 0; i < 16; i++) {
        int kk = i * 128 + (tid >> 2);
        int p  = tid & 3;
        uint4 v = *(const uint4*)&g_Wkn[kk][bn * 32 + p * 8];
        unsigned off = (unsigned)(kk >> 10) * 65536u
                     + (unsigned)p * 16384u + (unsigned)(kk & 1023) * 16u;
        *(uint4*)(smx + off) = v;
    }
    __syncthreads();

    // W ldmatrix lane addressing
    const int q   = lane >> 3;
    const int l7  = lane & 7;
    const int kgq = q >> 1;
    const unsigned wrowsel = (unsigned)((q & 1) * 8 + l7) * 16u;
    const unsigned whiBase = sb + (unsigned)kgq * 16384u + wrowsel;
    const unsigned wloBase = whiBase + 65536u;

    // partial-store mapping
    const int eg = lane >> 2;
    const int ei = lane & 3;
    // reduction / epilogue mapping
    const int r64 = tid >> 3;
    const int n0  = (tid & 7) * 4;

    const int bm4 = bm * 4;
    unsigned* const barp = &g_bar4[bm * 32];

    // epilogue constants
    const int gb    = bm * 64 + r64;
    const int tileE = gb >> 4;
    const int rloc  = gb & 15;
    const int Cb    = bn * 32 + n0;
    const int gE    = Cb >> 4;
    const int slot  = ((rloc & 8) ? 1 : 0) | ((Cb & 8) ? 2 : 0);
    const int L0    = ((rloc & 7) << 2) + ((n0 & 7) >> 1);
    const int wmE = r64 >> 5;
    const int rl  = r64 & 31;

    for (int t = 1; t < TT; t++) {
        const uint4* Ab = &g_Ap[(t + 1) & 1][0];

        // ---- pre-wait prologue (producer-independent) ----
        float* po = out + (long)gb * LDR + (long)t * HH + Cb;
        float4 x0p = *(const float4*)po;

        unsigned wh1[4], wh2[4], wl1[4], wl2[4];
        {
            const unsigned wko0 = (unsigned)kq * 256u;
            LDSM4T(wh1, whiBase + wko0);
            LDSM4T(wh2, whiBase + 32768u + wko0);
            LDSM4T(wl1, wloBase + wko0);
            LDSM4T(wl2, wloBase + 32768u + wko0);
        }

        float d[2][4][4];
        #pragma unroll
        for (int mi = 0; mi < 2; mi++)
            #pragma unroll
            for (int nt = 0; nt < 4; nt++)
                #pragma unroll
                for (int j = 0; j < 4; j++) d[mi][nt][j] = 0.f;

        // ---- warp-autonomous wait: producers published step t-1 ----
        if (t > 1) {
            const unsigned tgt = (unsigned)(t - 1) * 32u;
            while (acq_ldu(barp) < tgt) __nanosleep(32);
        }

        uint4 cur[2], nxt[2];
        #pragma unroll
        for (int mi = 0; mi < 2; mi++) {
            const int tl = bm4 + wm * 2 + mi;
            cur[mi] = Ab[(tl * 64 + kq) * 32 + lane];
        }

        #pragma unroll
        for (int i = 0; i < 8; i++) {
            if (i < 7) {
                const int gk1 = (i + 1) * 8 + kq;
                #pragma unroll
                for (int mi = 0; mi < 2; mi++) {
                    const int tl = bm4 + wm * 2 + mi;
                    nxt[mi] = Ab[(tl * 64 + gk1) * 32 + lane];
                }
            }

            const unsigned* a0 = (const unsigned*)&cur[0];
            const unsigned* a1 = (const unsigned*)&cur[1];

            // product group 1: A x Whi (reuse distance 8)
            mma16816h(d[0][0], a0, wh1[0], wh1[1]);
            mma16816h(d[0][1], a0, wh1[2], wh1[3]);
            mma16816h(d[0][2], a0, wh2[0], wh2[1]);
            mma16816h(d[0][3], a0, wh2[2], wh2[3]);
            mma16816h(d[1][0], a1, wh1[0], wh1[1]);
            mma16816h(d[1][1], a1, wh1[2], wh1[3]);
            mma16816h(d[1][2], a1, wh2[0], wh2[1]);
            mma16816h(d[1][3], a1, wh2[2], wh2[3]);
            // product group 2: A x Wlo
            mma16816h(d[0][0], a0, wl1[0], wl1[1]);
            mma16816h(d[0][1], a0, wl1[2], wl1[3]);
            mma16816h(d[0][2], a0, wl2[0], wl2[1]);
            mma16816h(d[0][3], a0, wl2[2], wl2[3]);
            mma16816h(d[1][0], a1, wl1[0], wl1[1]);
            mma16816h(d[1][1], a1, wl1[2], wl1[3]);
            mma16816h(d[1][2], a1, wl2[0], wl2[1]);
            mma16816h(d[1][3], a1, wl2[2], wl2[3]);

            if (i < 7) {
                const unsigned wko = (unsigned)((i + 1) * 8 + kq) * 256u;
                LDSM4T(wh1, whiBase + wko);
                LDSM4T(wh2, whiBase + 32768u + wko);
                LDSM4T(wl1, wloBase + wko);
                LDSM4T(wl2, wloBase + 32768u + wko);
                cur[0] = nxt[0];
                cur[1] = nxt[1];
            }
        }

        // ---- store m32xn32 fp32 partial (XOR-16 swizzle on rows) @128KB ----
        {
            const unsigned pb = 131072u + (unsigned)((wm * 8 + kq) * 4096);
            #pragma unroll
            for (int mi = 0; mi < 2; mi++) {
                #pragma unroll
                for (int half = 0; half < 2; half++) {
                    const int r = mi * 16 + eg + half * 8;
                    const unsigned xr = (unsigned)((r & 7) * 16);
                    #pragma unroll
                    for (int nt = 0; nt < 4; nt++) {
                        float2 pv;
                        pv.x = d[mi][nt][half * 2 + 0];
                        pv.y = d[mi][nt][half * 2 + 1];
                        unsigned cb = (unsigned)(nt * 32 + ei * 8) ^ xr;
                        *(float2*)(smx + pb + (unsigned)r * 128u + cb) = pv;
                    }
                }
            }
        }
        __syncthreads();                  // sync1: partials visible

        // ---- reduce 8 partials + fused epilogue ----
        float4 o0;
        {
            const unsigned xr = (unsigned)((rl & 7) * 16);
            const unsigned c0 = ((unsigned)(n0 * 4)) ^ xr;
            float4 s0 = {0.f, 0.f, 0.f, 0.f};
            #pragma unroll
            for (int p = 0; p < 8; p++) {
                const char* pp = smx + 131072u + (unsigned)((wmE * 8 + p) * 4096)
                               + (unsigned)rl * 128u;
                float4 a = *(const float4*)(pp + c0);
                s0.x += a.x; s0.y += a.y; s0.z += a.z; s0.w += a.w;
            }

            o0.x = fmaxf(x0p.x + s0.x, 0.f);
            o0.y = fmaxf(x0p.y + s0.y, 0.f);
            o0.z = fmaxf(x0p.z + s0.z, 0.f);
            o0.w = fmaxf(x0p.w + s0.w, 0.f);

            if (t < TT - 1) {
                // write next-step permuted fp16 fragments (the cross-CTA dep)
                unsigned* dh = (unsigned*)&g_Ap[t & 1][(tileE * 64 + gE) * 32];
                dh[(L0 + 0) * 4 + slot] = pack_h2(o0.x, o0.y);
                dh[(L0 + 1) * 4 + slot] = pack_h2(o0.z, o0.w);
            }
        }

        __syncthreads();                  // sync2: frag STGs issued + reads done
        if (t < TT - 1 && tid == 0) {
            __threadfence();
            atomicAdd(barp, 1u);
        }

        *(float4*)po = o0;                // out-store off the critical path
    }
}

// ---------------------------------------------------------------------------
extern "C" void kernel_launch(void* const* d_in, const int* in_sizes, int n_in,
                              void* d_out, int out_size)
{
    const float* x   = (const float*)d_in[0];
    const float* Wxh = (const float*)d_in[1];
    const float* bxh = (const float*)d_in[2];
    const float* Whh = (const float*)d_in[3];
    float* out = (float*)d_out;

    wx_convert<<<(EE * HH) / 256, 256>>>(Wxh);
    wt_convert<<<(HH * HH) / 256, 256>>>(Whh);

    const int smem_p1 = 2 * 32768;
    cudaFuncSetAttribute(gemm_xh_mma,
                         cudaFuncAttributeMaxDynamicSharedMemorySize, smem_p1);
    dim3 g1(HH / 128, (BB * TT) / 128);
    gemm_xh_mma<<<g1, 256, smem_p1>>>(x, bxh, out);

    init_h0<<<(BB * HH / 2) / 256, 256>>>(out);

    const int smem_p2 = 131072 + 65536;
    cudaFuncSetAttribute(rnn_scan_mma,
                         cudaFuncAttributeMaxDynamicSharedMemorySize, smem_p2);
    rnn_scan_mma<<<NCTA, 512, smem_p2>>>(out);

    bar_reset<<<1, 128>>>();
}

// round 16
// speedup vs baseline: 2.3674x; 1.0523x over previous
#include <cuda_runtime.h>
#include <cuda_bf16.h>
#include <cuda_fp16.h>

// Problem dims (fixed by the reference)
#define BB   256
#define TT   512
#define EE   512
#define HH   1024
#define LDR  ((long)TT * HH)

#define NCTA 128      // 4 M-tiles (64 rows) x 32 N-tiles (32 cols)

// ---------------------------------------------------------------------------
// Scratch (device globals; no allocation allowed)
// g_Ap[buf][(tile*64 + g)*32 + lane] : hidden state as fp16 PRE-PERMUTED mma
//   fragments (see round 15 comment).
// g_Wkn[kk][n]: Whh fp16 [k][n]: kk<1024 = hi, kk>=1024 = lo (residual).
// g_Wx[kk][n]:  Wxh fp16 [k][n]: kk<512  = hi, kk>=512  = lo (residual).
// ---------------------------------------------------------------------------
__device__ uint4 g_Ap[2][16 * 64 * 32];
__device__ __half g_Wkn[2048][HH];
__device__ __half g_Wx[1024][HH];

// ---------------------------------------------------------------------------
// PTX helpers
// ---------------------------------------------------------------------------
__device__ __forceinline__ unsigned smem_u32(const void* p) {
    unsigned a;
    asm("{ .reg .u64 t; cvta.to.shared.u64 t, %1; cvt.u32.u64 %0, t; }"
        : "=r"(a) : "l"(p));
    return a;
}

__device__ __forceinline__ unsigned acq_ldu(const unsigned* p) {
    unsigned v;
    asm volatile("ld.acquire.gpu.global.b32 %0, [%1];" : "=r"(v) : "l"(p));
    return v;
}

#define LDSM4(r, a) \
    asm volatile("ldmatrix.sync.aligned.m8n8.x4.shared.b16 {%0,%1,%2,%3}, [%4];" \
        : "=r"((r)[0]), "=r"((r)[1]), "=r"((r)[2]), "=r"((r)[3]) : "r"(a))

#define LDSM4T(r, a) \
    asm volatile("ldmatrix.sync.aligned.m8n8.x4.trans.shared.b16 {%0,%1,%2,%3}, [%4];" \
        : "=r"((r)[0]), "=r"((r)[1]), "=r"((r)[2]), "=r"((r)[3]) : "r"(a))

// fp16 mma
__device__ __forceinline__ void mma16816h(float* d, const unsigned* a,
                                          unsigned b0, unsigned b1) {
    asm volatile(
        "mma.sync.aligned.m16n8k16.row.col.f32.f16.f16.f32 "
        "{%0,%1,%2,%3}, {%4,%5,%6,%7}, {%8,%9}, {%0,%1,%2,%3};"
        : "+f"(d[0]), "+f"(d[1]), "+f"(d[2]), "+f"(d[3])
        : "r"(a[0]), "r"(a[1]), "r"(a[2]), "r"(a[3]), "r"(b0), "r"(b1));
}

__device__ __forceinline__ unsigned pack_h2(float v0, float v1) {
    __half2 h = __floats2half2_rn(v0, v1);
    return *(unsigned*)&h;
}

__device__ __forceinline__ uint4 pack8h(float4 a, float4 b) {
    uint4 r;
    r.x = pack_h2(a.x, a.y);
    r.y = pack_h2(a.z, a.w);
    r.z = pack_h2(b.x, b.y);
    r.w = pack_h2(b.z, b.w);
    return r;
}

// ---------------------------------------------------------------------------
// Per-bm-group barrier counters (4 independent groups of 32 CTAs)
// ---------------------------------------------------------------------------
__device__ unsigned int g_bar4[4 * 32];
__global__ void bar_reset() {
    if (threadIdx.x < 128) g_bar4[threadIdx.x] = 0;
}

// ---------------------------------------------------------------------------
// Prep kernels
// ---------------------------------------------------------------------------
__global__ void __launch_bounds__(256)
wt_convert(const float* __restrict__ Whh)
{
    int idx = blockIdx.x * 256 + threadIdx.x;
    int k = idx >> 10, n = idx & 1023;
    float w = Whh[(long)k * HH + n];
    __half hi = __float2half_rn(w);
    __half lo = __float2half_rn(w - __half2float(hi));
    g_Wkn[k][n] = hi;
    g_Wkn[1024 + k][n] = lo;
}

__global__ void __launch_bounds__(256)
wx_convert(const float* __restrict__ Wxh)
{
    int idx = blockIdx.x * 256 + threadIdx.x;
    int k = idx >> 10, n = idx & 1023;
    float w = Wxh[(long)k * HH + n];
    __half hi = __float2half_rn(w);
    __half lo = __float2half_rn(w - __half2float(hi));
    g_Wx[k][n] = hi;
    g_Wx[512 + k][n] = lo;
}

// h_0 = relu(xh_0) in place + permuted fp16 fragments into g_Ap[0]
__global__ void __launch_bounds__(256)
init_h0(float* __restrict__ out)
{
    int idx = blockIdx.x * 256 + threadIdx.x;   // 0 .. 128K-1
    int b  = idx >> 9;
    int c2 = (idx & 511) * 2;
    float* p = out + (long)b * LDR + c2;
    float v0 = fmaxf(p[0], 0.f);
    float v1 = fmaxf(p[1], 0.f);
    p[0] = v0; p[1] = v1;

    unsigned hw = pack_h2(v0, v1);

    int tile = b >> 4;
    int rloc = b & 15;
    int g    = c2 >> 4;
    int cb   = c2 & 15;
    int L    = ((rloc & 7) << 2) + ((cb & 7) >> 1);
    int slot = ((rloc & 8) ? 1 : 0) | ((cb & 8) ? 2 : 0);

    unsigned* dh = (unsigned*)&g_Ap[0][(tile * 64 + g) * 32 + L];
    dh[slot] = hw;
}

// ---------------------------------------------------------------------------
// Phase 1 (tensor): xh = x @ Wxh + bxh — fp16 2-product.
// CTA tile 128(m) x 128(n), K chunked by 32, double-buffered smem.
// Buffer (24KB): A fp16 @0 (8KB), Wxh-hi @8192, Wxh-lo @16384.
// ---------------------------------------------------------------------------
extern __shared__ char smx[];

#define AFX(kg, m) ((unsigned)((kg) * 2048 + ((m) >> 3) * 128 + ((((m) & 7) ^ (kg)) * 16)))

__global__ void __launch_bounds__(256)
gemm_xh_mma(const float* __restrict__ x,
            const float* __restrict__ bias,
            float* __restrict__ C)
{
    const int tid  = threadIdx.x;
    const int wid  = tid >> 5;
    const int lane = tid & 31;
    const int wr   = wid & 3;
    const int wc   = wid >> 2;
    const int bm   = blockIdx.y;
    const int bn   = blockIdx.x;

    const unsigned sb = smem_u32(smx);
    const int q   = lane >> 3;
    const int l7  = lane & 7;
    const int kgq = q >> 1;

    const int am = tid & 127;
    const int wk = tid & 31;

    float2 breg[8];
    #pragma unroll
    for (int n8 = 0; n8 < 8; n8++)
        breg[n8] = *(const float2*)&bias[bn * 128 + wc * 64 + n8 * 8 + (lane & 3) * 2];

    float acc[2][8][4];
    #pragma unroll
    for (int m = 0; m < 2; m++)
        #pragma unroll
        for (int n = 0; n < 8; n++)
            #pragma unroll
            for (int j = 0; j < 4; j++) acc[m][n][j] = 0.f;

    const float* xb = x + (long)(bm * 128) * EE;

    float4 xa[2][2];
    uint4  wvh[2], wvl[2];
    #pragma unroll
    for (int i = 0; i < 2; i++) {
        int idx = tid + i * 256;
        int kg = idx >> 7;
        const float* p = xb + (long)am * EE + kg * 8;
        xa[i][0] = *(const float4*)p;
        xa[i][1] = *(const float4*)(p + 4);
        int pp = (idx >> 5) & 15;
        wvh[i] = *(const uint4*)&g_Wx[wk][bn * 128 + pp * 8];
        wvl[i] = *(const uint4*)&g_Wx[512 + wk][bn * 128 + pp * 8];
    }
    #pragma unroll
    for (int i = 0; i < 2; i++) {
        int idx = tid + i * 256;
        int kg = idx >> 7;
        unsigned ao = AFX(kg, am);
        *(uint4*)(smx + ao) = pack8h(xa[i][0], xa[i][1]);
        int pp = (idx >> 5) & 15;
        unsigned wo = 8192u + (unsigned)pp * 512u + (unsigned)wk * 16u;
        *(uint4*)(smx + wo)        = wvh[i];
        *(uint4*)(smx + 8192 + wo) = wvl[i];
    }
    __syncthreads();

    unsigned buf = 0;
    for (int kc = 0; kc < 16; kc++) {
        const bool more = (kc + 1 < 16);
        if (more) {
            const int k0 = (kc + 1) * 32;
            #pragma unroll
            for (int i = 0; i < 2; i++) {
                int idx = tid + i * 256;
                int kg = idx >> 7;
                const float* p = xb + (long)am * EE + k0 + kg * 8;
                xa[i][0] = *(const float4*)p;
                xa[i][1] = *(const float4*)(p + 4);
                int pp = (idx >> 5) & 15;
                wvh[i] = *(const uint4*)&g_Wx[k0 + wk][bn * 128 + pp * 8];
                wvl[i] = *(const uint4*)&g_Wx[512 + k0 + wk][bn * 128 + pp * 8];
            }
        }

        const unsigned B0 = sb + buf * 24576u;
        #pragma unroll
        for (int s16 = 0; s16 < 2; s16++) {
            const int kg = s16 * 2 + kgq;
            const unsigned aoff = (unsigned)kg * 2048u + (unsigned)((l7 ^ kg) * 16);
            unsigned a0[4], a1[4];
            LDSM4(a0, B0 + aoff + (unsigned)(wr * 4 + 0 + (q & 1)) * 128u);
            LDSM4(a1, B0 + aoff + (unsigned)(wr * 4 + 2 + (q & 1)) * 128u);

            const unsigned wrow = (unsigned)(s16 * 16 + (q & 1) * 8 + l7) * 16u;
            #pragma unroll
            for (int pp = 0; pp < 4; pp++) {
                unsigned wh[4], wl[4];
                unsigned wbase = B0 + 8192u
                               + (unsigned)(wc * 8 + pp * 2 + kgq) * 512u + wrow;
                LDSM4T(wh, wbase);
                LDSM4T(wl, wbase + 8192u);
                const int n0 = pp * 2, n1 = pp * 2 + 1;
                mma16816h(acc[0][n0], a0, wh[0], wh[1]);
                mma16816h(acc[0][n1], a0, wh[2], wh[3]);
                mma16816h(acc[1][n0], a1, wh[0], wh[1]);
                mma16816h(acc[1][n1], a1, wh[2], wh[3]);
                mma16816h(acc[0][n0], a0, wl[0], wl[1]);
                mma16816h(acc[0][n1], a0, wl[2], wl[3]);
                mma16816h(acc[1][n0], a1, wl[0], wl[1]);
                mma16816h(acc[1][n1], a1, wl[2], wl[3]);
            }
        }

        if (more) {
            const unsigned nb = (buf ^ 1u) * 24576u;
            #pragma unroll
            for (int i = 0; i < 2; i++) {
                int idx = tid + i * 256;
                int kg = idx >> 7;
                unsigned ao = nb + AFX(kg, am);
                *(uint4*)(smx + ao) = pack8h(xa[i][0], xa[i][1]);
                int pp = (idx >> 5) & 15;
                unsigned wo = nb + 8192u + (unsigned)pp * 512u + (unsigned)wk * 16u;
                *(uint4*)(smx + wo)        = wvh[i];
                *(uint4*)(smx + 8192 + wo) = wvl[i];
            }
            __syncthreads();
            buf ^= 1u;
        }
    }

    #pragma unroll
    for (int mm = 0; mm < 2; mm++) {
        #pragma unroll
        for (int half = 0; half < 2; half++) {
            long row = (long)bm * 128 + wr * 32 + mm * 16 + (lane >> 2) + half * 8;
            float* pr = C + row * HH + bn * 128 + wc * 64 + (lane & 3) * 2;
            #pragma unroll
            for (int n8 = 0; n8 < 8; n8++) {
                float2 o;
                o.x = acc[mm][n8][half * 2 + 0] + breg[n8].x;
                o.y = acc[mm][n8][half * 2 + 1] + breg[n8].y;
                *(float2*)(pr + n8 * 8) = o;
            }
        }
    }
}

// ---------------------------------------------------------------------------
// Phase 2: persistent fp16 mma.sync scan (round-15, unchanged)
// ---------------------------------------------------------------------------
__global__ void __launch_bounds__(512, 1)
rnn_scan_mma(float* __restrict__ out)
{
    const int tid  = threadIdx.x;
    const int wid  = tid >> 5;
    const int kq   = wid & 7;
    const int wm   = wid >> 3;
    const int lane = tid & 31;
    const int bm   = blockIdx.x >> 5;
    const int bn   = blockIdx.x & 31;

    const unsigned sb = smem_u32(smx);

    // ---- stage W slice into SMEM panels (once): hi @0, lo @65536 ----
    for (int i = 0; i < 16; i++) {
        int kk = i * 128 + (tid >> 2);
        int p  = tid & 3;
        uint4 v = *(const uint4*)&g_Wkn[kk][bn * 32 + p * 8];
        unsigned off = (unsigned)(kk >> 10) * 65536u
                     + (unsigned)p * 16384u + (unsigned)(kk & 1023) * 16u;
        *(uint4*)(smx + off) = v;
    }
    __syncthreads();

    // W ldmatrix lane addressing
    const int q   = lane >> 3;
    const int l7  = lane & 7;
    const int kgq = q >> 1;
    const unsigned wrowsel = (unsigned)((q & 1) * 8 + l7) * 16u;
    const unsigned whiBase = sb + (unsigned)kgq * 16384u + wrowsel;
    const unsigned wloBase = whiBase + 65536u;

    // partial-store mapping
    const int eg = lane >> 2;
    const int ei = lane & 3;
    // reduction / epilogue mapping
    const int r64 = tid >> 3;
    const int n0  = (tid & 7) * 4;

    const int bm4 = bm * 4;
    unsigned* const barp = &g_bar4[bm * 32];

    // epilogue constants
    const int gb    = bm * 64 + r64;
    const int tileE = gb >> 4;
    const int rloc  = gb & 15;
    const int Cb    = bn * 32 + n0;
    const int gE    = Cb >> 4;
    const int slot  = ((rloc & 8) ? 1 : 0) | ((Cb & 8) ? 2 : 0);
    const int L0    = ((rloc & 7) << 2) + ((n0 & 7) >> 1);
    const int wmE = r64 >> 5;
    const int rl  = r64 & 31;

    for (int t = 1; t < TT; t++) {
        const uint4* Ab = &g_Ap[(t + 1) & 1][0];

        // ---- pre-wait prologue (producer-independent) ----
        float* po = out + (long)gb * LDR + (long)t * HH + Cb;
        float4 x0p = *(const float4*)po;

        unsigned wh1[4], wh2[4], wl1[4], wl2[4];
        {
            const unsigned wko0 = (unsigned)kq * 256u;
            LDSM4T(wh1, whiBase + wko0);
            LDSM4T(wh2, whiBase + 32768u + wko0);
            LDSM4T(wl1, wloBase + wko0);
            LDSM4T(wl2, wloBase + 32768u + wko0);
        }

        float d[2][4][4];
        #pragma unroll
        for (int mi = 0; mi < 2; mi++)
            #pragma unroll
            for (int nt = 0; nt < 4; nt++)
                #pragma unroll
                for (int j = 0; j < 4; j++) d[mi][nt][j] = 0.f;

        // ---- warp-autonomous wait: producers published step t-1 ----
        if (t > 1) {
            const unsigned tgt = (unsigned)(t - 1) * 32u;
            while (acq_ldu(barp) < tgt) __nanosleep(32);
        }

        uint4 cur[2], nxt[2];
        #pragma unroll
        for (int mi = 0; mi < 2; mi++) {
            const int tl = bm4 + wm * 2 + mi;
            cur[mi] = Ab[(tl * 64 + kq) * 32 + lane];
        }

        #pragma unroll
        for (int i = 0; i < 8; i++) {
            if (i < 7) {
                const int gk1 = (i + 1) * 8 + kq;
                #pragma unroll
                for (int mi = 0; mi < 2; mi++) {
                    const int tl = bm4 + wm * 2 + mi;
                    nxt[mi] = Ab[(tl * 64 + gk1) * 32 + lane];
                }
            }

            const unsigned* a0 = (const unsigned*)&cur[0];
            const unsigned* a1 = (const unsigned*)&cur[1];

            // product group 1: A x Whi (reuse distance 8)
            mma16816h(d[0][0], a0, wh1[0], wh1[1]);
            mma16816h(d[0][1], a0, wh1[2], wh1[3]);
            mma16816h(d[0][2], a0, wh2[0], wh2[1]);
            mma16816h(d[0][3], a0, wh2[2], wh2[3]);
            mma16816h(d[1][0], a1, wh1[0], wh1[1]);
            mma16816h(d[1][1], a1, wh1[2], wh1[3]);
            mma16816h(d[1][2], a1, wh2[0], wh2[1]);
            mma16816h(d[1][3], a1, wh2[2], wh2[3]);
            // product group 2: A x Wlo
            mma16816h(d[0][0], a0, wl1[0], wl1[1]);
            mma16816h(d[0][1], a0, wl1[2], wl1[3]);
            mma16816h(d[0][2], a0, wl2[0], wl2[1]);
            mma16816h(d[0][3], a0, wl2[2], wl2[3]);
            mma16816h(d[1][0], a1, wl1[0], wl1[1]);
            mma16816h(d[1][1], a1, wl1[2], wl1[3]);
            mma16816h(d[1][2], a1, wl2[0], wl2[1]);
            mma16816h(d[1][3], a1, wl2[2], wl2[3]);

            if (i < 7) {
                const unsigned wko = (unsigned)((i + 1) * 8 + kq) * 256u;
                LDSM4T(wh1, whiBase + wko);
                LDSM4T(wh2, whiBase + 32768u + wko);
                LDSM4T(wl1, wloBase + wko);
                LDSM4T(wl2, wloBase + 32768u + wko);
                cur[0] = nxt[0];
                cur[1] = nxt[1];
            }
        }

        // ---- store m32xn32 fp32 partial (XOR-16 swizzle on rows) @128KB ----
        {
            const unsigned pb = 131072u + (unsigned)((wm * 8 + kq) * 4096);
            #pragma unroll
            for (int mi = 0; mi < 2; mi++) {
                #pragma unroll
                for (int half = 0; half < 2; half++) {
                    const int r = mi * 16 + eg + half * 8;
                    const unsigned xr = (unsigned)((r & 7) * 16);
                    #pragma unroll
                    for (int nt = 0; nt < 4; nt++) {
                        float2 pv;
                        pv.x = d[mi][nt][half * 2 + 0];
                        pv.y = d[mi][nt][half * 2 + 1];
                        unsigned cb = (unsigned)(nt * 32 + ei * 8) ^ xr;
                        *(float2*)(smx + pb + (unsigned)r * 128u + cb) = pv;
                    }
                }
            }
        }
        __syncthreads();                  // sync1: partials visible

        // ---- reduce 8 partials + fused epilogue ----
        float4 o0;
        {
            const unsigned xr = (unsigned)((rl & 7) * 16);
            const unsigned c0 = ((unsigned)(n0 * 4)) ^ xr;
            float4 s0 = {0.f, 0.f, 0.f, 0.f};
            #pragma unroll
            for (int p = 0; p < 8; p++) {
                const char* pp = smx + 131072u + (unsigned)((wmE * 8 + p) * 4096)
                               + (unsigned)rl * 128u;
                float4 a = *(const float4*)(pp + c0);
                s0.x += a.x; s0.y += a.y; s0.z += a.z; s0.w += a.w;
            }

            o0.x = fmaxf(x0p.x + s0.x, 0.f);
            o0.y = fmaxf(x0p.y + s0.y, 0.f);
            o0.z = fmaxf(x0p.z + s0.z, 0.f);
            o0.w = fmaxf(x0p.w + s0.w, 0.f);

            if (t < TT - 1) {
                // write next-step permuted fp16 fragments (the cross-CTA dep)
                unsigned* dh = (unsigned*)&g_Ap[t & 1][(tileE * 64 + gE) * 32];
                dh[(L0 + 0) * 4 + slot] = pack_h2(o0.x, o0.y);
                dh[(L0 + 1) * 4 + slot] = pack_h2(o0.z, o0.w);
            }
        }

        __syncthreads();                  // sync2: frag STGs issued + reads done
        if (t < TT - 1 && tid == 0) {
            __threadfence();
            atomicAdd(barp, 1u);
        }

        *(float4*)po = o0;                // out-store off the critical path
    }
}

// ---------------------------------------------------------------------------
extern "C" void kernel_launch(void* const* d_in, const int* in_sizes, int n_in,
                              void* d_out, int out_size)
{
    const float* x   = (const float*)d_in[0];
    const float* Wxh = (const float*)d_in[1];
    const float* bxh = (const float*)d_in[2];
    const float* Whh = (const float*)d_in[3];
    float* out = (float*)d_out;

    wx_convert<<<(EE * HH) / 256, 256>>>(Wxh);
    wt_convert<<<(HH * HH) / 256, 256>>>(Whh);

    const int smem_p1 = 2 * 24576;
    cudaFuncSetAttribute(gemm_xh_mma,
                         cudaFuncAttributeMaxDynamicSharedMemorySize, smem_p1);
    dim3 g1(HH / 128, (BB * TT) / 128);
    gemm_xh_mma<<<g1, 256, smem_p1>>>(x, bxh, out);

    init_h0<<<(BB * HH / 2) / 256, 256>>>(out);

    const int smem_p2 = 131072 + 65536;
    cudaFuncSetAttribute(rnn_scan_mma,
                         cudaFuncAttributeMaxDynamicSharedMemorySize, smem_p2);
    rnn_scan_mma<<<NCTA, 512, smem_p2>>>(out);

    bar_reset<<<1, 128>>>();
}

// round 17
// speedup vs baseline: 2.5777x; 1.0888x over previous
#include <cuda_runtime.h>
#include <cuda_bf16.h>
#include <cuda_fp16.h>

// Problem dims (fixed by the reference)
#define BB   256
#define TT   512
#define EE   512
#define HH   1024
#define LDR  ((long)TT * HH)

#define NCTA 128      // 4 M-tiles (64 rows) x 32 N-tiles (32 cols)

// ---------------------------------------------------------------------------
// Scratch (device globals; no allocation allowed)
// g_Ap[buf][(tile*64 + g)*32 + lane] : hidden state as fp16 PRE-PERMUTED mma
//   fragments (see round 15 comment).
// g_Wkn[kk][n]: Whh fp16 [k][n]: kk<1024 = hi, kk>=1024 = lo (residual).
// g_Wx[kk][n]:  Wxh fp16 [k][n]: kk<512  = hi, kk>=512  = lo (residual).
// ---------------------------------------------------------------------------
__device__ uint4 g_Ap[2][16 * 64 * 32];
__device__ __half g_Wkn[2048][HH];
__device__ __half g_Wx[1024][HH];

// ---------------------------------------------------------------------------
// PTX helpers
// ---------------------------------------------------------------------------
__device__ __forceinline__ unsigned smem_u32(const void* p) {
    unsigned a;
    asm("{ .reg .u64 t; cvta.to.shared.u64 t, %1; cvt.u32.u64 %0, t; }"
        : "=r"(a) : "l"(p));
    return a;
}

__device__ __forceinline__ unsigned acq_ldu(const unsigned* p) {
    unsigned v;
    asm volatile("ld.acquire.gpu.global.b32 %0, [%1];" : "=r"(v) : "l"(p));
    return v;
}

#define LDSM4(r, a) \
    asm volatile("ldmatrix.sync.aligned.m8n8.x4.shared.b16 {%0,%1,%2,%3}, [%4];" \
        : "=r"((r)[0]), "=r"((r)[1]), "=r"((r)[2]), "=r"((r)[3]) : "r"(a))

#define LDSM4T(r, a) \
    asm volatile("ldmatrix.sync.aligned.m8n8.x4.trans.shared.b16 {%0,%1,%2,%3}, [%4];" \
        : "=r"((r)[0]), "=r"((r)[1]), "=r"((r)[2]), "=r"((r)[3]) : "r"(a))

// fp16 mma
__device__ __forceinline__ void mma16816h(float* d, const unsigned* a,
                                          unsigned b0, unsigned b1) {
    asm volatile(
        "mma.sync.aligned.m16n8k16.row.col.f32.f16.f16.f32 "
        "{%0,%1,%2,%3}, {%4,%5,%6,%7}, {%8,%9}, {%0,%1,%2,%3};"
        : "+f"(d[0]), "+f"(d[1]), "+f"(d[2]), "+f"(d[3])
        : "r"(a[0]), "r"(a[1]), "r"(a[2]), "r"(a[3]), "r"(b0), "r"(b1));
}

__device__ __forceinline__ unsigned pack_h2(float v0, float v1) {
    __half2 h = __floats2half2_rn(v0, v1);
    return *(unsigned*)&h;
}

__device__ __forceinline__ uint4 pack8h(float4 a, float4 b) {
    uint4 r;
    r.x = pack_h2(a.x, a.y);
    r.y = pack_h2(a.z, a.w);
    r.z = pack_h2(b.x, b.y);
    r.w = pack_h2(b.z, b.w);
    return r;
}

// ---------------------------------------------------------------------------
// Per-bm-group barrier counters (4 independent groups of 32 CTAs)
// ---------------------------------------------------------------------------
__device__ unsigned int g_bar4[4 * 32];
__global__ void bar_reset() {
    if (threadIdx.x < 128) g_bar4[threadIdx.x] = 0;
}

// ---------------------------------------------------------------------------
// Prep kernels
// ---------------------------------------------------------------------------
__global__ void __launch_bounds__(256)
wt_convert(const float* __restrict__ Whh)
{
    int idx = blockIdx.x * 256 + threadIdx.x;
    int k = idx >> 10, n = idx & 1023;
    float w = Whh[(long)k * HH + n];
    __half hi = __float2half_rn(w);
    __half lo = __float2half_rn(w - __half2float(hi));
    g_Wkn[k][n] = hi;
    g_Wkn[1024 + k][n] = lo;
}

__global__ void __launch_bounds__(256)
wx_convert(const float* __restrict__ Wxh)
{
    int idx = blockIdx.x * 256 + threadIdx.x;
    int k = idx >> 10, n = idx & 1023;
    float w = Wxh[(long)k * HH + n];
    __half hi = __float2half_rn(w);
    __half lo = __float2half_rn(w - __half2float(hi));
    g_Wx[k][n] = hi;
    g_Wx[512 + k][n] = lo;
}

// h_0 = relu(xh_0) in place + permuted fp16 fragments into g_Ap[0]
__global__ void __launch_bounds__(256)
init_h0(float* __restrict__ out)
{
    int idx = blockIdx.x * 256 + threadIdx.x;   // 0 .. 128K-1
    int b  = idx >> 9;
    int c2 = (idx & 511) * 2;
    float* p = out + (long)b * LDR + c2;
    float v0 = fmaxf(p[0], 0.f);
    float v1 = fmaxf(p[1], 0.f);
    p[0] = v0; p[1] = v1;

    unsigned hw = pack_h2(v0, v1);

    int tile = b >> 4;
    int rloc = b & 15;
    int g    = c2 >> 4;
    int cb   = c2 & 15;
    int L    = ((rloc & 7) << 2) + ((cb & 7) >> 1);
    int slot = ((rloc & 8) ? 1 : 0) | ((cb & 8) ? 2 : 0);

    unsigned* dh = (unsigned*)&g_Ap[0][(tile * 64 + g) * 32 + L];
    dh[slot] = hw;
}

// ---------------------------------------------------------------------------
// Phase 1 (tensor): xh = x @ Wxh + bxh — fp16 2-product, 512 threads.
// CTA tile 128(m) x 256(n), 16 warps (warp 32m x 64n), 4 warps/SMSP.
// Buffer (40KB): A fp16 @0 (8KB), Wxh-hi @8192 (16KB), Wxh-lo @24576 (16KB).
// ---------------------------------------------------------------------------
extern __shared__ char smx[];

#define AFX(kg, m) ((unsigned)((kg) * 2048 + ((m) >> 3) * 128 + ((((m) & 7) ^ (kg)) * 16)))

__global__ void __launch_bounds__(512)
gemm_xh_mma(const float* __restrict__ x,
            const float* __restrict__ bias,
            float* __restrict__ C)
{
    const int tid  = threadIdx.x;
    const int wid  = tid >> 5;
    const int lane = tid & 31;
    const int wr   = wid & 3;           // m quarter (32 rows)
    const int wc   = wid >> 2;          // n quarter (64 cols) 0..3
    const int bm   = blockIdx.y;        // 0..1023
    const int bn   = blockIdx.x;        // 0..3

    const unsigned sb = smem_u32(smx);
    const int q   = lane >> 3;
    const int l7  = lane & 7;
    const int kgq = q >> 1;

    // staging mapping
    const int am  = tid & 127;          // A m-row; kgA = tid>>7
    const int kgA = tid >> 7;
    const int wk  = tid & 31;           // W k-row; panels ppw, ppw+16
    const int ppw = tid >> 5;

    float2 breg[8];
    #pragma unroll
    for (int n8 = 0; n8 < 8; n8++)
        breg[n8] = *(const float2*)&bias[bn * 256 + wc * 64 + n8 * 8 + (lane & 3) * 2];

    float acc[2][8][4];
    #pragma unroll
    for (int m = 0; m < 2; m++)
        #pragma unroll
        for (int n = 0; n < 8; n++)
            #pragma unroll
            for (int j = 0; j < 4; j++) acc[m][n][j] = 0.f;

    const float* xb = x + (long)(bm * 128) * EE;

    float4 xa0, xa1;
    uint4  wvh0, wvh1, wvl0, wvl1;
    {
        const float* p = xb + (long)am * EE + kgA * 8;
        xa0 = *(const float4*)p;
        xa1 = *(const float4*)(p + 4);
        wvh0 = *(const uint4*)&g_Wx[wk][bn * 256 + ppw * 8];
        wvh1 = *(const uint4*)&g_Wx[wk][bn * 256 + (ppw + 16) * 8];
        wvl0 = *(const uint4*)&g_Wx[512 + wk][bn * 256 + ppw * 8];
        wvl1 = *(const uint4*)&g_Wx[512 + wk][bn * 256 + (ppw + 16) * 8];
    }
    {
        unsigned ao = AFX(kgA, am);
        *(uint4*)(smx + ao) = pack8h(xa0, xa1);
        unsigned wo = 8192u + (unsigned)ppw * 512u + (unsigned)wk * 16u;
        *(uint4*)(smx + wo)                 = wvh0;
        *(uint4*)(smx + wo + 16u * 512u)    = wvh1;
        *(uint4*)(smx + wo + 16384u)            = wvl0;
        *(uint4*)(smx + wo + 16384u + 16u * 512u) = wvl1;
    }
    __syncthreads();

    unsigned buf = 0;
    for (int kc = 0; kc < 16; kc++) {
        const bool more = (kc + 1 < 16);
        if (more) {
            const int k0 = (kc + 1) * 32;
            const float* p = xb + (long)am * EE + k0 + kgA * 8;
            xa0 = *(const float4*)p;
            xa1 = *(const float4*)(p + 4);
            wvh0 = *(const uint4*)&g_Wx[k0 + wk][bn * 256 + ppw * 8];
            wvh1 = *(const uint4*)&g_Wx[k0 + wk][bn * 256 + (ppw + 16) * 8];
            wvl0 = *(const uint4*)&g_Wx[512 + k0 + wk][bn * 256 + ppw * 8];
            wvl1 = *(const uint4*)&g_Wx[512 + k0 + wk][bn * 256 + (ppw + 16) * 8];
        }

        const unsigned B0 = sb + buf * 40960u;
        #pragma unroll
        for (int s16 = 0; s16 < 2; s16++) {
            const int kg = s16 * 2 + kgq;
            const unsigned aoff = (unsigned)kg * 2048u + (unsigned)((l7 ^ kg) * 16);
            unsigned a0[4], a1[4];
            LDSM4(a0, B0 + aoff + (unsigned)(wr * 4 + 0 + (q & 1)) * 128u);
            LDSM4(a1, B0 + aoff + (unsigned)(wr * 4 + 2 + (q & 1)) * 128u);

            const unsigned wrow = (unsigned)(s16 * 16 + (q & 1) * 8 + l7) * 16u;
            #pragma unroll
            for (int pp = 0; pp < 4; pp++) {
                unsigned wh[4], wl[4];
                unsigned wbase = B0 + 8192u
                               + (unsigned)(wc * 8 + pp * 2 + kgq) * 512u + wrow;
                LDSM4T(wh, wbase);
                LDSM4T(wl, wbase + 16384u);
                const int n0 = pp * 2, n1 = pp * 2 + 1;
                mma16816h(acc[0][n0], a0, wh[0], wh[1]);
                mma16816h(acc[0][n1], a0, wh[2], wh[3]);
                mma16816h(acc[1][n0], a1, wh[0], wh[1]);
                mma16816h(acc[1][n1], a1, wh[2], wh[3]);
                mma16816h(acc[0][n0], a0, wl[0], wl[1]);
                mma16816h(acc[0][n1], a0, wl[2], wl[3]);
                mma16816h(acc[1][n0], a1, wl[0], wl[1]);
                mma16816h(acc[1][n1], a1, wl[2], wl[3]);
            }
        }

        if (more) {
            const unsigned nb = (buf ^ 1u) * 40960u;
            unsigned ao = nb + AFX(kgA, am);
            *(uint4*)(smx + ao) = pack8h(xa0, xa1);
            unsigned wo = nb + 8192u + (unsigned)ppw * 512u + (unsigned)wk * 16u;
            *(uint4*)(smx + wo)                 = wvh0;
            *(uint4*)(smx + wo + 16u * 512u)    = wvh1;
            *(uint4*)(smx + wo + 16384u)            = wvl0;
            *(uint4*)(smx + wo + 16384u + 16u * 512u) = wvl1;
            __syncthreads();
            buf ^= 1u;
        }
    }

    #pragma unroll
    for (int mm = 0; mm < 2; mm++) {
        #pragma unroll
        for (int half = 0; half < 2; half++) {
            long row = (long)bm * 128 + wr * 32 + mm * 16 + (lane >> 2) + half * 8;
            float* pr = C + row * HH + bn * 256 + wc * 64 + (lane & 3) * 2;
            #pragma unroll
            for (int n8 = 0; n8 < 8; n8++) {
                float2 o;
                o.x = acc[mm][n8][half * 2 + 0] + breg[n8].x;
                o.y = acc[mm][n8][half * 2 + 1] + breg[n8].y;
                *(float2*)(pr + n8 * 8) = o;
            }
        }
    }
}

// ---------------------------------------------------------------------------
// Phase 2: persistent fp16 mma.sync scan (round-16 + per-half named sync1)
// ---------------------------------------------------------------------------
__global__ void __launch_bounds__(512, 1)
rnn_scan_mma(float* __restrict__ out)
{
    const int tid  = threadIdx.x;
    const int wid  = tid >> 5;
    const int kq   = wid & 7;
    const int wm   = wid >> 3;
    const int lane = tid & 31;
    const int bm   = blockIdx.x >> 5;
    const int bn   = blockIdx.x & 31;

    const unsigned sb = smem_u32(smx);

    // ---- stage W slice into SMEM panels (once): hi @0, lo @65536 ----
    for (int i = 0; i < 16; i++) {
        int kk = i * 128 + (tid >> 2);
        int p  = tid & 3;
        uint4 v = *(const uint4*)&g_Wkn[kk][bn * 32 + p * 8];
        unsigned off = (unsigned)(kk >> 10) * 65536u
                     + (unsigned)p * 16384u + (unsigned)(kk & 1023) * 16u;
        *(uint4*)(smx + off) = v;
    }
    __syncthreads();

    // W ldmatrix lane addressing
    const int q   = lane >> 3;
    const int l7  = lane & 7;
    const int kgq = q >> 1;
    const unsigned wrowsel = (unsigned)((q & 1) * 8 + l7) * 16u;
    const unsigned whiBase = sb + (unsigned)kgq * 16384u + wrowsel;
    const unsigned wloBase = whiBase + 65536u;

    // partial-store mapping
    const int eg = lane >> 2;
    const int ei = lane & 3;
    // reduction / epilogue mapping
    const int r64 = tid >> 3;
    const int n0  = (tid & 7) * 4;

    const int bm4 = bm * 4;
    unsigned* const barp = &g_bar4[bm * 32];

    // epilogue constants
    const int gb    = bm * 64 + r64;
    const int tileE = gb >> 4;
    const int rloc  = gb & 15;
    const int Cb    = bn * 32 + n0;
    const int gE    = Cb >> 4;
    const int slot  = ((rloc & 8) ? 1 : 0) | ((Cb & 8) ? 2 : 0);
    const int L0    = ((rloc & 7) << 2) + ((n0 & 7) >> 1);
    const int wmE = r64 >> 5;
    const int rl  = r64 & 31;

    for (int t = 1; t < TT; t++) {
        const uint4* Ab = &g_Ap[(t + 1) & 1][0];

        // ---- pre-wait prologue (producer-independent) ----
        float* po = out + (long)gb * LDR + (long)t * HH + Cb;
        float4 x0p = *(const float4*)po;

        unsigned wh1[4], wh2[4], wl1[4], wl2[4];
        {
            const unsigned wko0 = (unsigned)kq * 256u;
            LDSM4T(wh1, whiBase + wko0);
            LDSM4T(wh2, whiBase + 32768u + wko0);
            LDSM4T(wl1, wloBase + wko0);
            LDSM4T(wl2, wloBase + 32768u + wko0);
        }

        float d[2][4][4];
        #pragma unroll
        for (int mi = 0; mi < 2; mi++)
            #pragma unroll
            for (int nt = 0; nt < 4; nt++)
                #pragma unroll
                for (int j = 0; j < 4; j++) d[mi][nt][j] = 0.f;

        // ---- warp-autonomous wait: producers published step t-1 ----
        if (t > 1) {
            const unsigned tgt = (unsigned)(t - 1) * 32u;
            while (acq_ldu(barp) < tgt) __nanosleep(32);
        }

        uint4 cur[2], nxt[2];
        #pragma unroll
        for (int mi = 0; mi < 2; mi++) {
            const int tl = bm4 + wm * 2 + mi;
            cur[mi] = Ab[(tl * 64 + kq) * 32 + lane];
        }

        #pragma unroll
        for (int i = 0; i < 8; i++) {
            if (i < 7) {
                const int gk1 = (i + 1) * 8 + kq;
                #pragma unroll
                for (int mi = 0; mi < 2; mi++) {
                    const int tl = bm4 + wm * 2 + mi;
                    nxt[mi] = Ab[(tl * 64 + gk1) * 32 + lane];
                }
            }

            const unsigned* a0 = (const unsigned*)&cur[0];
            const unsigned* a1 = (const unsigned*)&cur[1];

            // product group 1: A x Whi (reuse distance 8)
            mma16816h(d[0][0], a0, wh1[0], wh1[1]);
            mma16816h(d[0][1], a0, wh1[2], wh1[3]);
            mma16816h(d[0][2], a0, wh2[0], wh2[1]);
            mma16816h(d[0][3], a0, wh2[2], wh2[3]);
            mma16816h(d[1][0], a1, wh1[0], wh1[1]);
            mma16816h(d[1][1], a1, wh1[2], wh1[3]);
            mma16816h(d[1][2], a1, wh2[0], wh2[1]);
            mma16816h(d[1][3], a1, wh2[2], wh2[3]);
            // product group 2: A x Wlo
            mma16816h(d[0][0], a0, wl1[0], wl1[1]);
            mma16816h(d[0][1], a0, wl1[2], wl1[3]);
            mma16816h(d[0][2], a0, wl2[0], wl2[1]);
            mma16816h(d[0][3], a0, wl2[2], wl2[3]);
            mma16816h(d[1][0], a1, wl1[0], wl1[1]);
            mma16816h(d[1][1], a1, wl1[2], wl1[3]);
            mma16816h(d[1][2], a1, wl2[0], wl2[1]);
            mma16816h(d[1][3], a1, wl2[2], wl2[3]);

            if (i < 7) {
                const unsigned wko = (unsigned)((i + 1) * 8 + kq) * 256u;
                LDSM4T(wh1, whiBase + wko);
                LDSM4T(wh2, whiBase + 32768u + wko);
                LDSM4T(wl1, wloBase + wko);
                LDSM4T(wl2, wloBase + 32768u + wko);
                cur[0] = nxt[0];
                cur[1] = nxt[1];
            }
        }

        // ---- store m32xn32 fp32 partial (XOR-16 swizzle on rows) @128KB ----
        {
            const unsigned pb = 131072u + (unsigned)((wm * 8 + kq) * 4096);
            #pragma unroll
            for (int mi = 0; mi < 2; mi++) {
                #pragma unroll
                for (int half = 0; half < 2; half++) {
                    const int r = mi * 16 + eg + half * 8;
                    const unsigned xr = (unsigned)((r & 7) * 16);
                    #pragma unroll
                    for (int nt = 0; nt < 4; nt++) {
                        float2 pv;
                        pv.x = d[mi][nt][half * 2 + 0];
                        pv.y = d[mi][nt][half * 2 + 1];
                        unsigned cb = (unsigned)(nt * 32 + ei * 8) ^ xr;
                        *(float2*)(smx + pb + (unsigned)r * 128u + cb) = pv;
                    }
                }
            }
        }
        // sync1 (per wm-half): stores of half -> reducers of same half
        if (wm == 0) asm volatile("bar.sync 1, 256;" ::: "memory");
        else         asm volatile("bar.sync 2, 256;" ::: "memory");

        // ---- reduce 8 partials + fused epilogue ----
        float4 o0;
        {
            const unsigned xr = (unsigned)((rl & 7) * 16);
            const unsigned c0 = ((unsigned)(n0 * 4)) ^ xr;
            float4 s0 = {0.f, 0.f, 0.f, 0.f};
            #pragma unroll
            for (int p = 0; p < 8; p++) {
                const char* pp = smx + 131072u + (unsigned)((wmE * 8 + p) * 4096)
                               + (unsigned)rl * 128u;
                float4 a = *(const float4*)(pp + c0);
                s0.x += a.x; s0.y += a.y; s0.z += a.z; s0.w += a.w;
            }

            o0.x = fmaxf(x0p.x + s0.x, 0.f);
            o0.y = fmaxf(x0p.y + s0.y, 0.f);
            o0.z = fmaxf(x0p.z + s0.z, 0.f);
            o0.w = fmaxf(x0p.w + s0.w, 0.f);

            if (t < TT - 1) {
                // write next-step permuted fp16 fragments (the cross-CTA dep)
                unsigned* dh = (unsigned*)&g_Ap[t & 1][(tileE * 64 + gE) * 32];
                dh[(L0 + 0) * 4 + slot] = pack_h2(o0.x, o0.y);
                dh[(L0 + 1) * 4 + slot] = pack_h2(o0.z, o0.w);
            }
        }

        __syncthreads();                  // sync2: frag STGs issued + reads done
        if (t < TT - 1 && tid == 0) {
            __threadfence();
            atomicAdd(barp, 1u);
        }

        *(float4*)po = o0;                // out-store off the critical path
    }
}

// ---------------------------------------------------------------------------
extern "C" void kernel_launch(void* const* d_in, const int* in_sizes, int n_in,
                              void* d_out, int out_size)
{
    const float* x   = (const float*)d_in[0];
    const float* Wxh = (const float*)d_in[1];
    const float* bxh = (const float*)d_in[2];
    const float* Whh = (const float*)d_in[3];
    float* out = (float*)d_out;

    wx_convert<<<(EE * HH) / 256, 256>>>(Wxh);
    wt_convert<<<(HH * HH) / 256, 256>>>(Whh);

    const int smem_p1 = 2 * 40960;
    cudaFuncSetAttribute(gemm_xh_mma,
                         cudaFuncAttributeMaxDynamicSharedMemorySize, smem_p1);
    dim3 g1(HH / 256, (BB * TT) / 128);          // (4, 1024)
    gemm_xh_mma<<<g1, 512, smem_p1>>>(x, bxh, out);

    init_h0<<<(BB * HH / 2) / 256, 256>>>(out);

    const int smem_p2 = 131072 + 65536;
    cudaFuncSetAttribute(rnn_scan_mma,
                         cudaFuncAttributeMaxDynamicSharedMemorySize, smem_p2);
    rnn_scan_mma<<<NCTA, 512, smem_p2>>>(out);

    bar_reset<<<1, 128>>>();
}